// round 2
// baseline (speedup 1.0000x reference)
#include <cuda_runtime.h>
#include <cuda_bf16.h>

#define NN 100000
#define NE 800000
#define FIN 256
#define HID 128
#define NCLS 32

// ---------------- scratch (device globals; no allocation allowed) ----------------
__device__ int   g_cnt[NN];
__device__ int   g_rowptr[NN];
__device__ int   g_cursor[NN];
__device__ int   g_part[128];
__device__ float g_dinv[NN];
__device__ int   g_csr[NE];
__device__ int   g_is64;
__device__ __align__(16) float g_xw1[(size_t)NN * HID];   // X @ W1
__device__ __align__(16) float g_h[(size_t)NN * HID];     // relu(agg1)
__device__ __align__(16) float g_xw2[(size_t)NN * NCLS];  // h @ W2

// ---------------- helpers ----------------
__device__ __forceinline__ int load_idx(const void* p, long long i, int is64) {
    if (is64) return (int)((const long long*)p)[i];
    return ((const int*)p)[i];
}

__device__ __forceinline__ unsigned f2tf(float x) {
    unsigned r;
    asm("cvt.rna.tf32.f32 %0, %1;" : "=r"(r) : "f"(x));
    return r;
}

__device__ __forceinline__ void mma_tf32(float c[4], unsigned a0, unsigned a1,
                                         unsigned a2, unsigned a3,
                                         unsigned b0, unsigned b1) {
    asm volatile(
        "mma.sync.aligned.m16n8k8.row.col.f32.tf32.tf32.f32 "
        "{%0,%1,%2,%3}, {%4,%5,%6,%7}, {%8,%9}, {%0,%1,%2,%3};"
        : "+f"(c[0]), "+f"(c[1]), "+f"(c[2]), "+f"(c[3])
        : "r"(a0), "r"(a1), "r"(a2), "r"(a3), "r"(b0), "r"(b1));
}

// ---------------- preprocessing ----------------
__global__ void k_zero_detect(const void* __restrict__ ei, int n) {
    int i = blockIdx.x * blockDim.x + threadIdx.x;
    if (i < n) g_cnt[i] = 0;
    if (i == 0) {
        const long long* p = (const long long*)ei;
        int ok = 1;
        for (int j = 0; j < 256; j++) {
            long long v = p[j];
            if (v < 0 || v >= NN) { ok = 0; break; }
        }
        g_is64 = ok;
    }
}

__global__ void k_hist(const void* __restrict__ ei, int e) {
    int i = blockIdx.x * blockDim.x + threadIdx.x;
    int is64 = g_is64;
    if (i < e) {
        int d = load_idx(ei, (long long)e + i, is64);
        atomicAdd(&g_cnt[d], 1);
    }
}

__device__ __forceinline__ int block_exscan(int v, int* p_total) {
    const int lane = threadIdx.x & 31, w = threadIdx.x >> 5;
    const int nw = blockDim.x >> 5;
    __shared__ int wsum[32];
    int x = v;
#pragma unroll
    for (int o = 1; o < 32; o <<= 1) {
        int y = __shfl_up_sync(0xffffffffu, x, o);
        if (lane >= o) x += y;
    }
    if (lane == 31) wsum[w] = x;
    __syncthreads();
    if (w == 0) {
        int s = (lane < nw) ? wsum[lane] : 0;
#pragma unroll
        for (int o = 1; o < 32; o <<= 1) {
            int y = __shfl_up_sync(0xffffffffu, s, o);
            if (lane >= o) s += y;
        }
        wsum[lane] = s;
    }
    __syncthreads();
    int base = (w > 0) ? wsum[w - 1] : 0;
    *p_total = wsum[31];
    return base + (x - v);
}

__global__ void k_scan1(int n) {
    int i = blockIdx.x * blockDim.x + threadIdx.x;
    int v = (i < n) ? g_cnt[i] : 0;
    int total;
    int ex = block_exscan(v, &total);
    if (i < n) g_rowptr[i] = ex;
    if (threadIdx.x == 0) g_part[blockIdx.x] = total;
}

__global__ void k_scan2(int nb) {
    int i = threadIdx.x;
    int v = (i < nb) ? g_part[i] : 0;
    int total;
    int ex = block_exscan(v, &total);
    if (i < nb) g_part[i] = ex;
}

__global__ void k_scan3(int n) {
    int i = blockIdx.x * blockDim.x + threadIdx.x;
    if (i < n) {
        int rp = g_rowptr[i] + g_part[blockIdx.x];
        g_rowptr[i] = rp;
        g_cursor[i] = rp;
        g_dinv[i] = rsqrtf((float)(g_cnt[i] + 1));  // +1: self loop
    }
}

__global__ void k_scatter(const void* __restrict__ ei, int e) {
    int i = blockIdx.x * blockDim.x + threadIdx.x;
    int is64 = g_is64;
    if (i < e) {
        int s = load_idx(ei, i, is64);
        int d = load_idx(ei, (long long)e + i, is64);
        int pos = atomicAdd(&g_cursor[d], 1);
        g_csr[pos] = s;
    }
}

// ---------------- GEMM1: xw1 = X[100k,256] @ W1[256,128]  (tf32 mma) ----------------
// Block: 128 rows x 128 cols, BK=16. 8 warps: warp grid 4(m) x 2(n), warp tile 32x64.
// Smem A in fragment-permuted order [kstep(2)][mtile(8)][lane(32)][4 vals]
// Smem B in fragment-permuted order [kstep(2)][ntile(16)][lane(32)][2 vals]
#define G1_BM 128

__global__ __launch_bounds__(256, 2) void k_gemm1(const float* __restrict__ X,
                                                  const float* __restrict__ W, int n) {
    __shared__ unsigned As[2 * 8 * 32 * 4];   // 8 KB
    __shared__ unsigned Bs[2 * 16 * 32 * 2];  // 4 KB
    const int tid = threadIdx.x, lane = tid & 31, warp = tid >> 5;
    const int wm = warp & 3, wn = warp >> 2;
    const int row0 = blockIdx.x * G1_BM;

    float c[2][8][4];
#pragma unroll
    for (int i = 0; i < 2; i++)
#pragma unroll
        for (int j = 0; j < 8; j++)
#pragma unroll
            for (int v = 0; v < 4; v++) c[i][j][v] = 0.f;

    // per-thread loader constants
    // A: f = tid + j*256 -> m = f>>2, kq = (f&3)*4
    int am[2], akq[2], abase[2];
#pragma unroll
    for (int j = 0; j < 2; j++) {
        int f = tid + j * 256;
        int m = f >> 2, kq = (f & 3) * 4;
        am[j] = m; akq[j] = kq;
        int mtile = m >> 4, rg = m & 7, hi = (m >> 3) & 1;
        int kstep = kq >> 3, kh = (kq >> 2) & 1;
        int val = hi + 2 * kh;
        abase[j] = ((kstep * 8 + mtile) * 32 + rg * 4) * 4 + val;  // + cc*4
    }
    // B: f = tid + j*256 -> k = f>>5, c4 = (f&31)*4
    int bk[2], bc4[2], bbase[2];
#pragma unroll
    for (int j = 0; j < 2; j++) {
        int f = tid + j * 256;
        int k = f >> 5, c4 = (f & 31) * 4;
        bk[j] = k; bc4[j] = c4;
        int tg = k & 3, bv = (k & 7) >> 2, kstep = k >> 3;
        int ntile = c4 >> 3, g0 = c4 & 7;
        bbase[j] = ((kstep * 16 + ntile) * 32 + g0 * 4 + tg) * 2 + bv;  // + cc*8
    }

    float4 aval[2], bval[2];
    // prefetch k0 = 0
#pragma unroll
    for (int j = 0; j < 2; j++) {
        int r = row0 + am[j]; if (r >= n) r = n - 1;
        aval[j] = *(const float4*)&X[(size_t)r * FIN + akq[j]];
        bval[j] = *(const float4*)&W[(size_t)bk[j] * HID + bc4[j]];
    }

    for (int k0 = 0; k0 < FIN; k0 += 16) {
        __syncthreads();
#pragma unroll
        for (int j = 0; j < 2; j++) {
            As[abase[j] + 0 * 4] = f2tf(aval[j].x);
            As[abase[j] + 1 * 4] = f2tf(aval[j].y);
            As[abase[j] + 2 * 4] = f2tf(aval[j].z);
            As[abase[j] + 3 * 4] = f2tf(aval[j].w);
            Bs[bbase[j] + 0 * 8] = f2tf(bval[j].x);
            Bs[bbase[j] + 1 * 8] = f2tf(bval[j].y);
            Bs[bbase[j] + 2 * 8] = f2tf(bval[j].z);
            Bs[bbase[j] + 3 * 8] = f2tf(bval[j].w);
        }
        __syncthreads();
        if (k0 + 16 < FIN) {
#pragma unroll
            for (int j = 0; j < 2; j++) {
                int r = row0 + am[j]; if (r >= n) r = n - 1;
                aval[j] = *(const float4*)&X[(size_t)r * FIN + k0 + 16 + akq[j]];
                bval[j] = *(const float4*)&W[(size_t)(k0 + 16 + bk[j]) * HID + bc4[j]];
            }
        }
#pragma unroll
        for (int ks = 0; ks < 2; ks++) {
            uint4 a[2];
#pragma unroll
            for (int i = 0; i < 2; i++)
                a[i] = *(const uint4*)&As[((ks * 8 + wm * 2 + i) * 32 + lane) * 4];
            uint2 b[8];
#pragma unroll
            for (int j = 0; j < 8; j++)
                b[j] = *(const uint2*)&Bs[((ks * 16 + wn * 8 + j) * 32 + lane) * 2];
#pragma unroll
            for (int i = 0; i < 2; i++)
#pragma unroll
                for (int j = 0; j < 8; j++)
                    mma_tf32(c[i][j], a[i].x, a[i].y, a[i].z, a[i].w, b[j].x, b[j].y);
        }
    }

    const int g = lane >> 2, tg = lane & 3;
#pragma unroll
    for (int i = 0; i < 2; i++) {
        int rlo = row0 + wm * 32 + i * 16 + g;
        int rhi = rlo + 8;
#pragma unroll
        for (int j = 0; j < 8; j++) {
            int col = wn * 64 + j * 8 + tg * 2;
            if (rlo < n)
                *(float2*)&g_xw1[(size_t)rlo * HID + col] = make_float2(c[i][j][0], c[i][j][1]);
            if (rhi < n)
                *(float2*)&g_xw1[(size_t)rhi * HID + col] = make_float2(c[i][j][2], c[i][j][3]);
        }
    }
}

// ---------------- Agg1: h = relu(Ahat @ xw1 + b1), warp per node ----------------
__global__ void k_agg1(const float* __restrict__ b1, int n) {
    int gt = blockIdx.x * blockDim.x + threadIdx.x;
    int node = gt >> 5;
    int lane = threadIdx.x & 31;
    if (node >= n) return;
    int start = g_rowptr[node];
    int cnt = g_cnt[node];
    float di = g_dinv[node];
    float4 v = ((const float4*)&g_xw1[(size_t)node * HID])[lane];
    float4 acc = make_float4(di * v.x, di * v.y, di * v.z, di * v.w);  // self loop
    for (int e = 0; e < cnt; e++) {
        int s = g_csr[start + e];
        float ds = g_dinv[s];
        float4 w = ((const float4*)&g_xw1[(size_t)s * HID])[lane];
        acc.x = fmaf(ds, w.x, acc.x);
        acc.y = fmaf(ds, w.y, acc.y);
        acc.z = fmaf(ds, w.z, acc.z);
        acc.w = fmaf(ds, w.w, acc.w);
    }
    float4 bb = ((const float4*)b1)[lane];
    float4 o;
    o.x = fmaxf(fmaf(di, acc.x, bb.x), 0.f);
    o.y = fmaxf(fmaf(di, acc.y, bb.y), 0.f);
    o.z = fmaxf(fmaf(di, acc.z, bb.z), 0.f);
    o.w = fmaxf(fmaf(di, acc.w, bb.w), 0.f);
    ((float4*)&g_h[(size_t)node * HID])[lane] = o;
}

// ---------------- GEMM2: xw2 = h[100k,128] @ W2[128,32]  (tf32 mma) ----------------
// Block: 128 rows, BK=32. 8 warps: warp w -> rows w*16..w*16+15, all 32 cols (4 ntiles).
#define G2_BM 128

__global__ __launch_bounds__(256, 2) void k_gemm2(const float* __restrict__ W, int n) {
    __shared__ unsigned As[4 * 8 * 32 * 4];  // 16 KB [kstep(4)][mtile(8)][lane][4]
    __shared__ unsigned Bs[4 * 4 * 32 * 2];  // 4 KB  [kstep(4)][ntile(4)][lane][2]
    const int tid = threadIdx.x, lane = tid & 31, warp = tid >> 5;
    const int row0 = blockIdx.x * G2_BM;

    float c[4][4];
#pragma unroll
    for (int j = 0; j < 4; j++)
#pragma unroll
        for (int v = 0; v < 4; v++) c[j][v] = 0.f;

    // A loader: 4 f4/thread. f = tid + j*256 -> m = f>>3, kq = (f&7)*4
    int am[4], akq[4], abase[4];
#pragma unroll
    for (int j = 0; j < 4; j++) {
        int f = tid + j * 256;
        int m = f >> 3, kq = (f & 7) * 4;
        am[j] = m; akq[j] = kq;
        int mtile = m >> 4, rg = m & 7, hi = (m >> 3) & 1;
        int kstep = kq >> 3, kh = (kq >> 2) & 1;
        int val = hi + 2 * kh;
        abase[j] = ((kstep * 8 + mtile) * 32 + rg * 4) * 4 + val;
    }
    // B loader: 1 f4/thread. f = tid -> k = f>>3, c4 = (f&7)*4
    int bkk = tid >> 3, bc4 = (tid & 7) * 4;
    int btg = bkk & 3, bbv = (bkk & 7) >> 2, bks = bkk >> 3;
    int bnt = bc4 >> 3, bg0 = bc4 & 7;
    int bbase = ((bks * 4 + bnt) * 32 + bg0 * 4 + btg) * 2 + bbv;

    float4 aval[4], bval;
#pragma unroll
    for (int j = 0; j < 4; j++) {
        int r = row0 + am[j]; if (r >= n) r = n - 1;
        aval[j] = *(const float4*)&g_h[(size_t)r * HID + akq[j]];
    }
    bval = *(const float4*)&W[(size_t)bkk * NCLS + bc4];

    for (int k0 = 0; k0 < HID; k0 += 32) {
        __syncthreads();
#pragma unroll
        for (int j = 0; j < 4; j++) {
            As[abase[j] + 0 * 4] = f2tf(aval[j].x);
            As[abase[j] + 1 * 4] = f2tf(aval[j].y);
            As[abase[j] + 2 * 4] = f2tf(aval[j].z);
            As[abase[j] + 3 * 4] = f2tf(aval[j].w);
        }
        Bs[bbase + 0 * 8] = f2tf(bval.x);
        Bs[bbase + 1 * 8] = f2tf(bval.y);
        Bs[bbase + 2 * 8] = f2tf(bval.z);
        Bs[bbase + 3 * 8] = f2tf(bval.w);
        __syncthreads();
        if (k0 + 32 < HID) {
#pragma unroll
            for (int j = 0; j < 4; j++) {
                int r = row0 + am[j]; if (r >= n) r = n - 1;
                aval[j] = *(const float4*)&g_h[(size_t)r * HID + k0 + 32 + akq[j]];
            }
            bval = *(const float4*)&W[(size_t)(k0 + 32 + bkk) * NCLS + bc4];
        }
#pragma unroll
        for (int ks = 0; ks < 4; ks++) {
            uint4 a = *(const uint4*)&As[((ks * 8 + warp) * 32 + lane) * 4];
#pragma unroll
            for (int j = 0; j < 4; j++) {
                uint2 b = *(const uint2*)&Bs[((ks * 4 + j) * 32 + lane) * 2];
                mma_tf32(c[j], a.x, a.y, a.z, a.w, b.x, b.y);
            }
        }
    }

    const int g = lane >> 2, tg = lane & 3;
    int rlo = row0 + warp * 16 + g;
    int rhi = rlo + 8;
#pragma unroll
    for (int j = 0; j < 4; j++) {
        int col = j * 8 + tg * 2;
        if (rlo < n) *(float2*)&g_xw2[(size_t)rlo * NCLS + col] = make_float2(c[j][0], c[j][1]);
        if (rhi < n) *(float2*)&g_xw2[(size_t)rhi * NCLS + col] = make_float2(c[j][2], c[j][3]);
    }
}

// ---------------- Agg2 + log_softmax, warp per node ----------------
__global__ void k_agg2(const float* __restrict__ b2, float* __restrict__ out, int n) {
    int gt = blockIdx.x * blockDim.x + threadIdx.x;
    int node = gt >> 5;
    int lane = threadIdx.x & 31;
    if (node >= n) return;
    int start = g_rowptr[node];
    int cnt = g_cnt[node];
    float di = g_dinv[node];
    float acc = di * g_xw2[(size_t)node * NCLS + lane];  // self loop
    for (int e = 0; e < cnt; e++) {
        int s = g_csr[start + e];
        float ds = g_dinv[s];
        acc = fmaf(ds, g_xw2[(size_t)s * NCLS + lane], acc);
    }
    float v = fmaf(di, acc, b2[lane]);
    float m = v;
#pragma unroll
    for (int o = 16; o > 0; o >>= 1) m = fmaxf(m, __shfl_xor_sync(0xffffffffu, m, o));
    float ex = __expf(v - m);
    float s = ex;
#pragma unroll
    for (int o = 16; o > 0; o >>= 1) s += __shfl_xor_sync(0xffffffffu, s, o);
    out[(size_t)node * NCLS + lane] = v - m - logf(s);
}

// ---------------- launch ----------------
extern "C" void kernel_launch(void* const* d_in, const int* in_sizes, int n_in,
                              void* d_out, int out_size) {
    const float* X = (const float*)d_in[0];
    const void* EI = d_in[1];
    const float* W1 = (const float*)d_in[2];
    const float* b1 = (const float*)d_in[3];
    const float* W2 = (const float*)d_in[4];
    const float* b2 = (const float*)d_in[5];
    float* out = (float*)d_out;

    int n = in_sizes[0] / FIN;   // 100000
    int e = in_sizes[1] / 2;     // 800000

    k_zero_detect<<<(n + 255) / 256, 256>>>(EI, n);
    k_hist<<<(e + 255) / 256, 256>>>(EI, e);
    int scan_blocks = (n + 1023) / 1024;  // 98
    k_scan1<<<scan_blocks, 1024>>>(n);
    k_scan2<<<1, 128>>>(scan_blocks);
    k_scan3<<<scan_blocks, 1024>>>(n);
    k_scatter<<<(e + 255) / 256, 256>>>(EI, e);

    k_gemm1<<<(n + G1_BM - 1) / G1_BM, 256>>>(X, W1, n);
    k_agg1<<<(n * 32 + 255) / 256, 256>>>(b1, n);
    k_gemm2<<<(n + G2_BM - 1) / G2_BM, 256>>>(W2, n);
    k_agg2<<<(n * 32 + 255) / 256, 256>>>(b2, out, n);
}

// round 4
// speedup vs baseline: 1.0410x; 1.0410x over previous
#include <cuda_runtime.h>
#include <cuda_bf16.h>

#define NN 100000
#define NE 800000
#define FIN 256
#define HID 128
#define NCLS 32

typedef unsigned long long ull;

// ---------------- scratch (device globals; no allocation allowed) ----------------
__device__ int   g_cnt[NN];
__device__ int   g_rowptr[NN];
__device__ int   g_cursor[NN];
__device__ int   g_part[128];
__device__ float g_dinv[NN];
__device__ int   g_csr[NE];
__device__ int   g_is64;
__device__ __align__(16) float g_xw1[(size_t)NN * HID];   // X @ W1
__device__ __align__(16) float g_h[(size_t)NN * HID];     // relu(agg1)
__device__ __align__(16) float g_xw2[(size_t)NN * NCLS];  // h @ W2

// ---------------- packed f32x2 helpers ----------------
__device__ __forceinline__ void fma2(ull& d, ull a, ull b) {
    asm("fma.rn.f32x2 %0, %1, %2, %0;" : "+l"(d) : "l"(a), "l"(b));
}
__device__ __forceinline__ ull dup2(float x) {
    ull r;
    asm("mov.b64 %0, {%1, %1};" : "=l"(r) : "f"(x));
    return r;
}
__device__ __forceinline__ float2 unpk(ull v) {
    float2 r;
    asm("mov.b64 {%0, %1}, %2;" : "=f"(r.x), "=f"(r.y) : "l"(v));
    return r;
}

// ---------------- edge index helpers (int32/int64 agnostic) ----------------
__device__ __forceinline__ int load_idx(const void* p, long long i, int is64) {
    if (is64) return (int)((const long long*)p)[i];
    return ((const int*)p)[i];
}

__global__ void k_zero_detect(const void* __restrict__ ei, int n) {
    int i = blockIdx.x * blockDim.x + threadIdx.x;
    if (i < n) g_cnt[i] = 0;
    if (i == 0) {
        const long long* p = (const long long*)ei;
        int ok = 1;
        for (int j = 0; j < 256; j++) {
            long long v = p[j];
            if (v < 0 || v >= NN) { ok = 0; break; }
        }
        g_is64 = ok;
    }
}

__global__ void k_hist(const void* __restrict__ ei, int e) {
    int i = blockIdx.x * blockDim.x + threadIdx.x;
    int is64 = g_is64;
    if (i < e) {
        int d = load_idx(ei, (long long)e + i, is64);
        atomicAdd(&g_cnt[d], 1);
    }
}

// ---------------- block exclusive scan ----------------
__device__ __forceinline__ int block_exscan(int v, int* p_total) {
    const int lane = threadIdx.x & 31, w = threadIdx.x >> 5;
    const int nw = blockDim.x >> 5;
    __shared__ int wsum[32];
    int x = v;
#pragma unroll
    for (int o = 1; o < 32; o <<= 1) {
        int y = __shfl_up_sync(0xffffffffu, x, o);
        if (lane >= o) x += y;
    }
    if (lane == 31) wsum[w] = x;
    __syncthreads();
    if (w == 0) {
        int s = (lane < nw) ? wsum[lane] : 0;
#pragma unroll
        for (int o = 1; o < 32; o <<= 1) {
            int y = __shfl_up_sync(0xffffffffu, s, o);
            if (lane >= o) s += y;
        }
        wsum[lane] = s;
    }
    __syncthreads();
    int base = (w > 0) ? wsum[w - 1] : 0;
    *p_total = wsum[31];
    return base + (x - v);
}

__global__ void k_scan1(int n) {
    int i = blockIdx.x * blockDim.x + threadIdx.x;
    int v = (i < n) ? g_cnt[i] : 0;
    int total;
    int ex = block_exscan(v, &total);
    if (i < n) g_rowptr[i] = ex;
    if (threadIdx.x == 0) g_part[blockIdx.x] = total;
}

__global__ void k_scan2(int nb) {
    int i = threadIdx.x;
    int v = (i < nb) ? g_part[i] : 0;
    int total;
    int ex = block_exscan(v, &total);
    if (i < nb) g_part[i] = ex;
}

__global__ void k_scan3(int n) {
    int i = blockIdx.x * blockDim.x + threadIdx.x;
    if (i < n) {
        int rp = g_rowptr[i] + g_part[blockIdx.x];
        g_rowptr[i] = rp;
        g_cursor[i] = rp;
        g_dinv[i] = rsqrtf((float)(g_cnt[i] + 1));  // +1: self loop
    }
}

__global__ void k_scatter(const void* __restrict__ ei, int e) {
    int i = blockIdx.x * blockDim.x + threadIdx.x;
    int is64 = g_is64;
    if (i < e) {
        int s = load_idx(ei, i, is64);
        int d = load_idx(ei, (long long)e + i, is64);
        int pos = atomicAdd(&g_cursor[d], 1);
        g_csr[pos] = s;
    }
}

// ---------------- GEMM1: xw1 = X[100k,256] @ W1[256,128]  (fma.f32x2) ----------------
#define G1_BM 64
#define G1_BN 128
#define G1_BK 16

__global__ __launch_bounds__(256) void k_gemm1(const float* __restrict__ X,
                                               const float* __restrict__ W, int n) {
    __shared__ float Xs[G1_BK][G1_BM + 4];  // transposed, padded (stride 68*4=272B, 16B-mult)
    __shared__ float Ws[G1_BK][G1_BN];
    const int tid = threadIdx.x;
    const int row0 = blockIdx.x * G1_BM;
    const int warp = tid >> 5, lane = tid & 31;
    const int wm = warp >> 2, wn = warp & 3;  // 2 x 4 warps
    const int tm = lane >> 3, tn = lane & 7;  // 4 x 8 lanes

    // acc2[i][j]: rows (tm*8+2i, tm*8+2i+1) packed, col wn*32+tn*4+j
    ull acc2[4][4];
#pragma unroll
    for (int i = 0; i < 4; i++)
#pragma unroll
        for (int j = 0; j < 4; j++) acc2[i][j] = 0ull;

    const int ldr = tid >> 2;          // 0..63  (row in tile)
    const int ldk = (tid & 3) * 4;     // 0,4,8,12 (k group)
    int xrow = row0 + ldr; if (xrow >= n) xrow = n - 1;

    for (int k0 = 0; k0 < FIN; k0 += G1_BK) {
        float4 xv = *(const float4*)&X[(size_t)xrow * FIN + k0 + ldk];
        Xs[ldk + 0][ldr] = xv.x;
        Xs[ldk + 1][ldr] = xv.y;
        Xs[ldk + 2][ldr] = xv.z;
        Xs[ldk + 3][ldr] = xv.w;
#pragma unroll
        for (int j = 0; j < 2; j++) {
            int f = tid + j * 256;          // float4 idx 0..511
            int kk = f >> 5, c4 = (f & 31) * 4;
            *(float4*)&Ws[kk][c4] = *(const float4*)&W[(k0 + kk) * G1_BN + c4];
        }
        __syncthreads();
#pragma unroll
        for (int kk = 0; kk < G1_BK; kk++) {
            // A: 8 consecutive rows -> 4 natural f32x2 pairs (16B-aligned)
            ulonglong2 a01 = *(const ulonglong2*)&Xs[kk][wm * 32 + tm * 8];
            ulonglong2 a23 = *(const ulonglong2*)&Xs[kk][wm * 32 + tm * 8 + 4];
            float4 b = *(const float4*)&Ws[kk][wn * 32 + tn * 4];
            ull ap[4] = {a01.x, a01.y, a23.x, a23.y};
            ull bd[4] = {dup2(b.x), dup2(b.y), dup2(b.z), dup2(b.w)};
#pragma unroll
            for (int i = 0; i < 4; i++)
#pragma unroll
                for (int j = 0; j < 4; j++) fma2(acc2[i][j], ap[i], bd[j]);
        }
        __syncthreads();
    }
    const int rbase = row0 + wm * 32 + tm * 8;
    const int col = wn * 32 + tn * 4;
#pragma unroll
    for (int i = 0; i < 4; i++) {
        float2 v0 = unpk(acc2[i][0]), v1 = unpk(acc2[i][1]);
        float2 v2 = unpk(acc2[i][2]), v3 = unpk(acc2[i][3]);
        int r0 = rbase + 2 * i, r1 = r0 + 1;
        if (r0 < n)
            *(float4*)&g_xw1[(size_t)r0 * HID + col] = make_float4(v0.x, v1.x, v2.x, v3.x);
        if (r1 < n)
            *(float4*)&g_xw1[(size_t)r1 * HID + col] = make_float4(v0.y, v1.y, v2.y, v3.y);
    }
}

// ---------------- Agg1: h = relu(Ahat @ xw1 + b1), warp per node ----------------
__global__ void k_agg1(const float* __restrict__ b1, int n) {
    int gt = blockIdx.x * blockDim.x + threadIdx.x;
    int node = gt >> 5;
    int lane = threadIdx.x & 31;
    if (node >= n) return;
    int start = g_rowptr[node];
    int cnt = g_cnt[node];
    float di = g_dinv[node];
    float4 v = ((const float4*)&g_xw1[(size_t)node * HID])[lane];
    float4 acc = make_float4(di * v.x, di * v.y, di * v.z, di * v.w);  // self loop
    for (int e = 0; e < cnt; e++) {
        int s = g_csr[start + e];
        float ds = g_dinv[s];
        float4 w = ((const float4*)&g_xw1[(size_t)s * HID])[lane];
        acc.x = fmaf(ds, w.x, acc.x);
        acc.y = fmaf(ds, w.y, acc.y);
        acc.z = fmaf(ds, w.z, acc.z);
        acc.w = fmaf(ds, w.w, acc.w);
    }
    float4 bb = ((const float4*)b1)[lane];
    float4 o;
    o.x = fmaxf(fmaf(di, acc.x, bb.x), 0.f);
    o.y = fmaxf(fmaf(di, acc.y, bb.y), 0.f);
    o.z = fmaxf(fmaf(di, acc.z, bb.z), 0.f);
    o.w = fmaxf(fmaf(di, acc.w, bb.w), 0.f);
    ((float4*)&g_h[(size_t)node * HID])[lane] = o;
}

// ---------------- GEMM2: xw2 = h[100k,128] @ W2[128,32]  (fma.f32x2) ----------------
#define G2_BM 64
#define G2_BK 16

__global__ __launch_bounds__(256) void k_gemm2(const float* __restrict__ W, int n) {
    __shared__ float Hs[G2_BK][G2_BM + 4];
    __shared__ float Ws[G2_BK][NCLS];
    const int tid = threadIdx.x;
    const int row0 = blockIdx.x * G2_BM;
    const int warp = tid >> 5, lane = tid & 31;  // warp w -> rows w*8..w*8+7, col = lane

    // acc2[i]: rows (warp*8+2i, +1) packed, col = lane
    ull acc2[4];
#pragma unroll
    for (int i = 0; i < 4; i++) acc2[i] = 0ull;

    const int ldr = tid >> 2;
    const int ldk = (tid & 3) * 4;
    int hrow = row0 + ldr; if (hrow >= n) hrow = n - 1;

    for (int k0 = 0; k0 < HID; k0 += G2_BK) {
        float4 hv = *(const float4*)&g_h[(size_t)hrow * HID + k0 + ldk];
        Hs[ldk + 0][ldr] = hv.x;
        Hs[ldk + 1][ldr] = hv.y;
        Hs[ldk + 2][ldr] = hv.z;
        Hs[ldk + 3][ldr] = hv.w;
        {   // W2 tile 16x32 = 512 floats, one float2/thread
            int kk = tid >> 4, c = (tid & 15) * 2;
            *(float2*)&Ws[kk][c] = *(const float2*)&W[(k0 + kk) * NCLS + c];
        }
        __syncthreads();
#pragma unroll
        for (int kk = 0; kk < G2_BK; kk++) {
            ull bd = dup2(Ws[kk][lane]);
            ulonglong2 a01 = *(const ulonglong2*)&Hs[kk][warp * 8];
            ulonglong2 a23 = *(const ulonglong2*)&Hs[kk][warp * 8 + 4];
            fma2(acc2[0], a01.x, bd);
            fma2(acc2[1], a01.y, bd);
            fma2(acc2[2], a23.x, bd);
            fma2(acc2[3], a23.y, bd);
        }
        __syncthreads();
    }
#pragma unroll
    for (int i = 0; i < 4; i++) {
        float2 v = unpk(acc2[i]);
        int r0 = row0 + warp * 8 + 2 * i, r1 = r0 + 1;
        if (r0 < n) g_xw2[(size_t)r0 * NCLS + lane] = v.x;
        if (r1 < n) g_xw2[(size_t)r1 * NCLS + lane] = v.y;
    }
}

// ---------------- Agg2 + log_softmax, warp per node ----------------
__global__ void k_agg2(const float* __restrict__ b2, float* __restrict__ out, int n) {
    int gt = blockIdx.x * blockDim.x + threadIdx.x;
    int node = gt >> 5;
    int lane = threadIdx.x & 31;
    if (node >= n) return;
    int start = g_rowptr[node];
    int cnt = g_cnt[node];
    float di = g_dinv[node];
    float acc = di * g_xw2[(size_t)node * NCLS + lane];  // self loop
    for (int e = 0; e < cnt; e++) {
        int s = g_csr[start + e];
        float ds = g_dinv[s];
        acc = fmaf(ds, g_xw2[(size_t)s * NCLS + lane], acc);
    }
    float v = fmaf(di, acc, b2[lane]);
    float m = v;
#pragma unroll
    for (int o = 16; o > 0; o >>= 1) m = fmaxf(m, __shfl_xor_sync(0xffffffffu, m, o));
    float ex = __expf(v - m);
    float s = ex;
#pragma unroll
    for (int o = 16; o > 0; o >>= 1) s += __shfl_xor_sync(0xffffffffu, s, o);
    out[(size_t)node * NCLS + lane] = v - m - logf(s);
}

// ---------------- launch ----------------
extern "C" void kernel_launch(void* const* d_in, const int* in_sizes, int n_in,
                              void* d_out, int out_size) {
    const float* X = (const float*)d_in[0];
    const void* EI = d_in[1];
    const float* W1 = (const float*)d_in[2];
    const float* b1 = (const float*)d_in[3];
    const float* W2 = (const float*)d_in[4];
    const float* b2 = (const float*)d_in[5];
    float* out = (float*)d_out;

    int n = in_sizes[0] / FIN;   // 100000
    int e = in_sizes[1] / 2;     // 800000

    k_zero_detect<<<(n + 255) / 256, 256>>>(EI, n);
    k_hist<<<(e + 255) / 256, 256>>>(EI, e);
    int scan_blocks = (n + 1023) / 1024;  // 98
    k_scan1<<<scan_blocks, 1024>>>(n);
    k_scan2<<<1, 128>>>(scan_blocks);
    k_scan3<<<scan_blocks, 1024>>>(n);
    k_scatter<<<(e + 255) / 256, 256>>>(EI, e);

    k_gemm1<<<(n + G1_BM - 1) / G1_BM, 256>>>(X, W1, n);
    k_agg1<<<(n * 32 + 255) / 256, 256>>>(b1, n);
    k_gemm2<<<(n + G2_BM - 1) / G2_BM, 256>>>(W2, n);
    k_agg2<<<(n * 32 + 255) / 256, 256>>>(b2, out, n);
}

// round 5
// speedup vs baseline: 1.2264x; 1.1781x over previous
#include <cuda_runtime.h>
#include <cuda_bf16.h>

#define NN 100000
#define NE 800000
#define FIN 256
#define HID 128
#define NCLS 32
#define NPRE 128           // preproc blocks inside fat kernel (<=148 -> all wave-1 resident)

// ---------------- scratch (device globals; no allocation allowed) ----------------
__device__ int   g_cnt[NN];
__device__ int   g_rowptr[NN];
__device__ int   g_cursor[NN];
__device__ int   g_part[NPRE];
__device__ float g_dinv[NN];
__device__ int   g_csr[NE];
__device__ int   g_is64;
__device__ unsigned g_bar_cnt = 0;
__device__ volatile unsigned g_bar_gen = 0;
__device__ __align__(16) float g_xw1[(size_t)NN * HID];   // X @ W1
__device__ __align__(16) float g_h[(size_t)NN * HID];     // relu(agg1)
__device__ __align__(16) float g_xw2[(size_t)NN * NCLS];  // h @ W2

// ---------------- helpers ----------------
__device__ __forceinline__ int load_idx(const void* p, long long i, int is64) {
    if (is64) return (int)((const long long*)p)[i];
    return ((const int*)p)[i];
}

// grid barrier among the NPRE preproc blocks (all resident in wave 1)
__device__ __forceinline__ void pre_grid_bar() {
    __syncthreads();
    if (threadIdx.x == 0) {
        __threadfence();
        unsigned g = g_bar_gen;
        if (atomicAdd(&g_bar_cnt, 1u) == NPRE - 1) {
            g_bar_cnt = 0;
            __threadfence();
            g_bar_gen = g + 1;
        } else {
            while (g_bar_gen == g) { __nanosleep(64); }
        }
    }
    __syncthreads();
}

__device__ __forceinline__ int block_exscan(int v, int* p_total, int* wsum) {
    const int lane = threadIdx.x & 31, w = threadIdx.x >> 5;
    const int nw = blockDim.x >> 5;
    int x = v;
#pragma unroll
    for (int o = 1; o < 32; o <<= 1) {
        int y = __shfl_up_sync(0xffffffffu, x, o);
        if (lane >= o) x += y;
    }
    if (lane == 31) wsum[w] = x;
    __syncthreads();
    if (w == 0) {
        int s = (lane < nw) ? wsum[lane] : 0;
#pragma unroll
        for (int o = 1; o < 32; o <<= 1) {
            int y = __shfl_up_sync(0xffffffffu, s, o);
            if (lane >= o) s += y;
        }
        wsum[lane] = s;
    }
    __syncthreads();
    int base = (w > 0) ? wsum[w - 1] : 0;
    *p_total = wsum[31];
    __syncthreads();
    return base + (x - v);
}

// ================= FAT KERNEL: preproc (blocks 0..NPRE-1) + GEMM1 (rest) =================
__global__ __launch_bounds__(256) void k_fat(const float* __restrict__ X,
                                             const float* __restrict__ W1,
                                             const void* __restrict__ ei,
                                             int n, int e) {
    __shared__ float As[2][16][132];   // [buf][k][m] transposed, padded
    __shared__ float Bs[2][16][128];   // [buf][k][n]
    __shared__ int   p_wsum[32];
    __shared__ int   p_boff;
    const int tid = threadIdx.x;

    if (blockIdx.x < NPRE) {
        // ---------------- preprocessing path ----------------
        const int gt = blockIdx.x * 256 + tid;
        const int GT = NPRE * 256;
        // phase 0: zero counts + detect dtype
        for (int i = gt; i < n; i += GT) g_cnt[i] = 0;
        if (gt == 0) {
            const long long* p = (const long long*)ei;
            int ok = 1;
            for (int j = 0; j < 256; j++) {
                long long v = p[j];
                if (v < 0 || v >= n) { ok = 0; break; }
            }
            g_is64 = ok;
        }
        pre_grid_bar();
        // phase 1: histogram of dst
        const int is64 = (int)__ldcg(&g_is64);
        for (int i = gt; i < e; i += GT) {
            int d = load_idx(ei, (long long)e + i, is64);
            atomicAdd(&g_cnt[d], 1);
        }
        pre_grid_bar();
        // phase 2: scan (thread-chunked)
        const int L = (n + GT - 1) / GT;
        const int base = gt * L;
        const int end = (base + L < n) ? base + L : n;
        int s = 0;
        for (int i = base; i < end; i++) s += __ldcg(&g_cnt[i]);
        int tot;
        int ex = block_exscan(s, &tot, p_wsum);
        if (tid == 0) g_part[blockIdx.x] = tot;
        pre_grid_bar();
        {
            int v = (tid < NPRE) ? __ldcg(&g_part[tid]) : 0;
            int t2;
            int ex2 = block_exscan(v, &t2, p_wsum);
            if (tid == (int)blockIdx.x) p_boff = ex2;
            __syncthreads();
            int run = p_boff + ex;
            for (int i = base; i < end; i++) {
                int c = __ldcg(&g_cnt[i]);
                g_rowptr[i] = run;
                g_cursor[i] = run;
                g_dinv[i] = rsqrtf((float)(c + 1));  // +1 self loop
                run += c;
            }
        }
        pre_grid_bar();
        // phase 3: scatter src by dst
        for (int i = gt; i < e; i += GT) {
            int s0 = load_idx(ei, i, is64);
            int d0 = load_idx(ei, (long long)e + i, is64);
            int pos = atomicAdd(&g_cursor[d0], 1);
            g_csr[pos] = s0;
        }
        return;
    }

    // ---------------- GEMM1 path: 128x128 tile, 8x8 microtile, BK=16, double-buffered ----------------
    const int bid = blockIdx.x - NPRE;
    const int row0 = bid * 128;
    const int ty = tid >> 4;   // 0..15
    const int tx = tid & 15;   // 0..15

    float c[8][8];
#pragma unroll
    for (int i = 0; i < 8; i++)
#pragma unroll
        for (int j = 0; j < 8; j++) c[i][j] = 0.f;

    const int arow_l = tid >> 1;        // 0..127
    const int akq = (tid & 1) * 8;      // 0 or 8
    int arow = row0 + arow_l; if (arow >= n) arow = n - 1;
    const float* aptr = X + (size_t)arow * FIN + akq;
    const int bkb = tid >> 5;           // 0..7
    const int bc4 = (tid & 31) * 4;     // 0..124

    float4 ra0, ra1, rb0, rb1;
#define G1_GLOAD(kt) do {                                           \
        int _k0 = (kt) * 16;                                        \
        ra0 = *(const float4*)(aptr + _k0);                         \
        ra1 = *(const float4*)(aptr + _k0 + 4);                     \
        rb0 = *(const float4*)&W1[(size_t)(_k0 + bkb) * HID + bc4]; \
        rb1 = *(const float4*)&W1[(size_t)(_k0 + 8 + bkb) * HID + bc4]; \
    } while (0)
#define G1_STS(b) do {                          \
        As[b][akq + 0][arow_l] = ra0.x;         \
        As[b][akq + 1][arow_l] = ra0.y;         \
        As[b][akq + 2][arow_l] = ra0.z;         \
        As[b][akq + 3][arow_l] = ra0.w;         \
        As[b][akq + 4][arow_l] = ra1.x;         \
        As[b][akq + 5][arow_l] = ra1.y;         \
        As[b][akq + 6][arow_l] = ra1.z;         \
        As[b][akq + 7][arow_l] = ra1.w;         \
        *(float4*)&Bs[b][bkb][bc4] = rb0;       \
        *(float4*)&Bs[b][8 + bkb][bc4] = rb1;   \
    } while (0)

    G1_GLOAD(0);
    G1_STS(0);
    for (int kt = 0; kt < FIN / 16; kt++) {
        __syncthreads();
        if (kt + 1 < FIN / 16) G1_GLOAD(kt + 1);
        const int b = kt & 1;
#pragma unroll
        for (int kk = 0; kk < 16; kk++) {
            float4 a0 = *(const float4*)&As[b][kk][ty * 4];
            float4 a1 = *(const float4*)&As[b][kk][64 + ty * 4];
            float4 b0 = *(const float4*)&Bs[b][kk][tx * 4];
            float4 b1 = *(const float4*)&Bs[b][kk][64 + tx * 4];
            float av[8] = {a0.x, a0.y, a0.z, a0.w, a1.x, a1.y, a1.z, a1.w};
            float bv[8] = {b0.x, b0.y, b0.z, b0.w, b1.x, b1.y, b1.z, b1.w};
#pragma unroll
            for (int i = 0; i < 8; i++)
#pragma unroll
                for (int j = 0; j < 8; j++) c[i][j] = fmaf(av[i], bv[j], c[i][j]);
        }
        if (kt + 1 < FIN / 16) G1_STS((kt + 1) & 1);
    }

#pragma unroll
    for (int ih = 0; ih < 2; ih++)
#pragma unroll
        for (int i = 0; i < 4; i++) {
            int r = row0 + ih * 64 + ty * 4 + i;
            if (r < n) {
                int ci = ih * 4 + i;
                *(float4*)&g_xw1[(size_t)r * HID + tx * 4] =
                    make_float4(c[ci][0], c[ci][1], c[ci][2], c[ci][3]);
                *(float4*)&g_xw1[(size_t)r * HID + 64 + tx * 4] =
                    make_float4(c[ci][4], c[ci][5], c[ci][6], c[ci][7]);
            }
        }
}

// ---------------- Agg1: h = relu(Ahat @ xw1 + b1), warp per node, 2-way unrolled ----------------
__global__ void k_agg1(const float* __restrict__ b1, int n) {
    int gt = blockIdx.x * blockDim.x + threadIdx.x;
    int node = gt >> 5;
    int lane = threadIdx.x & 31;
    if (node >= n) return;
    int start = g_rowptr[node];
    int cnt = g_cnt[node];
    float di = g_dinv[node];
    float4 v = ((const float4*)&g_xw1[(size_t)node * HID])[lane];
    float4 acc = make_float4(di * v.x, di * v.y, di * v.z, di * v.w);  // self loop
    int t = 0;
    for (; t + 2 <= cnt; t += 2) {
        int s0 = g_csr[start + t], s1 = g_csr[start + t + 1];
        float d0 = g_dinv[s0], d1 = g_dinv[s1];
        float4 w0 = ((const float4*)&g_xw1[(size_t)s0 * HID])[lane];
        float4 w1 = ((const float4*)&g_xw1[(size_t)s1 * HID])[lane];
        acc.x = fmaf(d0, w0.x, fmaf(d1, w1.x, acc.x));
        acc.y = fmaf(d0, w0.y, fmaf(d1, w1.y, acc.y));
        acc.z = fmaf(d0, w0.z, fmaf(d1, w1.z, acc.z));
        acc.w = fmaf(d0, w0.w, fmaf(d1, w1.w, acc.w));
    }
    if (t < cnt) {
        int s0 = g_csr[start + t];
        float d0 = g_dinv[s0];
        float4 w0 = ((const float4*)&g_xw1[(size_t)s0 * HID])[lane];
        acc.x = fmaf(d0, w0.x, acc.x);
        acc.y = fmaf(d0, w0.y, acc.y);
        acc.z = fmaf(d0, w0.z, acc.z);
        acc.w = fmaf(d0, w0.w, acc.w);
    }
    float4 bb = ((const float4*)b1)[lane];
    float4 o;
    o.x = fmaxf(fmaf(di, acc.x, bb.x), 0.f);
    o.y = fmaxf(fmaf(di, acc.y, bb.y), 0.f);
    o.z = fmaxf(fmaf(di, acc.z, bb.z), 0.f);
    o.w = fmaxf(fmaf(di, acc.w, bb.w), 0.f);
    ((float4*)&g_h[(size_t)node * HID])[lane] = o;
}

// ---------------- GEMM2: xw2 = h[100k,128] @ W2[128,32], 4x4 microtile ----------------
__global__ __launch_bounds__(256) void k_gemm2(const float* __restrict__ W, int n) {
    __shared__ float As[2][16][132];
    __shared__ float Bs[2][16][32];
    const int tid = threadIdx.x;
    const int row0 = blockIdx.x * 128;
    const int ty = tid >> 3;   // 0..31 -> rows ty*4..+3
    const int tx = tid & 7;    // 0..7  -> cols tx*4..+3

    float c[4][4];
#pragma unroll
    for (int i = 0; i < 4; i++)
#pragma unroll
        for (int j = 0; j < 4; j++) c[i][j] = 0.f;

    const int arow_l = tid >> 1;
    const int akq = (tid & 1) * 8;
    int arow = row0 + arow_l; if (arow >= n) arow = n - 1;
    const float* aptr = g_h + (size_t)arow * HID + akq;
    const int bkb = tid >> 3;          // 0..31 (only tid<128 loads B)
    const int bc4 = (tid & 7) * 4;

    float4 ra0, ra1, rb;
#define G2_GLOAD(kt) do {                                            \
        int _k0 = (kt) * 16;                                         \
        ra0 = *(const float4*)(aptr + _k0);                          \
        ra1 = *(const float4*)(aptr + _k0 + 4);                      \
        if (tid < 128) rb = *(const float4*)&W[(size_t)(_k0 + bkb) * NCLS + bc4]; \
    } while (0)
#define G2_STS(b) do {                          \
        As[b][akq + 0][arow_l] = ra0.x;         \
        As[b][akq + 1][arow_l] = ra0.y;         \
        As[b][akq + 2][arow_l] = ra0.z;         \
        As[b][akq + 3][arow_l] = ra0.w;         \
        As[b][akq + 4][arow_l] = ra1.x;         \
        As[b][akq + 5][arow_l] = ra1.y;         \
        As[b][akq + 6][arow_l] = ra1.z;         \
        As[b][akq + 7][arow_l] = ra1.w;         \
        if (tid < 128) *(float4*)&Bs[b][bkb][bc4] = rb; \
    } while (0)

    G2_GLOAD(0);
    G2_STS(0);
    for (int kt = 0; kt < HID / 16; kt++) {
        __syncthreads();
        if (kt + 1 < HID / 16) G2_GLOAD(kt + 1);
        const int b = kt & 1;
#pragma unroll
        for (int kk = 0; kk < 16; kk++) {
            float4 a = *(const float4*)&As[b][kk][ty * 4];
            float4 bb = *(const float4*)&Bs[b][kk][tx * 4];
            float av[4] = {a.x, a.y, a.z, a.w};
            float bv[4] = {bb.x, bb.y, bb.z, bb.w};
#pragma unroll
            for (int i = 0; i < 4; i++)
#pragma unroll
                for (int j = 0; j < 4; j++) c[i][j] = fmaf(av[i], bv[j], c[i][j]);
        }
        if (kt + 1 < HID / 16) G2_STS((kt + 1) & 1);
    }

#pragma unroll
    for (int i = 0; i < 4; i++) {
        int r = row0 + ty * 4 + i;
        if (r < n)
            *(float4*)&g_xw2[(size_t)r * NCLS + tx * 4] =
                make_float4(c[i][0], c[i][1], c[i][2], c[i][3]);
    }
}

// ---------------- Agg2 + log_softmax, warp per node ----------------
__global__ void k_agg2(const float* __restrict__ b2, float* __restrict__ out, int n) {
    int gt = blockIdx.x * blockDim.x + threadIdx.x;
    int node = gt >> 5;
    int lane = threadIdx.x & 31;
    if (node >= n) return;
    int start = g_rowptr[node];
    int cnt = g_cnt[node];
    float di = g_dinv[node];
    float acc = di * g_xw2[(size_t)node * NCLS + lane];  // self loop
    int t = 0;
    for (; t + 2 <= cnt; t += 2) {
        int s0 = g_csr[start + t], s1 = g_csr[start + t + 1];
        float d0 = g_dinv[s0], d1 = g_dinv[s1];
        float w0 = g_xw2[(size_t)s0 * NCLS + lane];
        float w1 = g_xw2[(size_t)s1 * NCLS + lane];
        acc = fmaf(d0, w0, fmaf(d1, w1, acc));
    }
    if (t < cnt) {
        int s0 = g_csr[start + t];
        acc = fmaf(g_dinv[s0], g_xw2[(size_t)s0 * NCLS + lane], acc);
    }
    float v = fmaf(di, acc, b2[lane]);
    float m = v;
#pragma unroll
    for (int o = 16; o > 0; o >>= 1) m = fmaxf(m, __shfl_xor_sync(0xffffffffu, m, o));
    float ex = __expf(v - m);
    float s = ex;
#pragma unroll
    for (int o = 16; o > 0; o >>= 1) s += __shfl_xor_sync(0xffffffffu, s, o);
    out[(size_t)node * NCLS + lane] = v - m - logf(s);
}

// ---------------- launch ----------------
extern "C" void kernel_launch(void* const* d_in, const int* in_sizes, int n_in,
                              void* d_out, int out_size) {
    const float* X = (const float*)d_in[0];
    const void* EI = d_in[1];
    const float* W1 = (const float*)d_in[2];
    const float* b1 = (const float*)d_in[3];
    const float* W2 = (const float*)d_in[4];
    const float* b2 = (const float*)d_in[5];
    float* out = (float*)d_out;

    int n = in_sizes[0] / FIN;   // 100000
    int e = in_sizes[1] / 2;     // 800000

    int g1blocks = (n + 127) / 128;  // 782
    k_fat<<<NPRE + g1blocks, 256>>>(X, W1, EI, n, e);
    k_agg1<<<(n * 32 + 255) / 256, 256>>>(b1, n);
    k_gemm2<<<(n + 127) / 128, 256>>>(W2, n);
    k_agg2<<<(n * 32 + 255) / 256, 256>>>(b2, out, n);
}

// round 6
// speedup vs baseline: 1.3959x; 1.1382x over previous
#include <cuda_runtime.h>
#include <cuda_fp16.h>
#include <cstdint>

#define NN 100000
#define NE 800000
#define FIN 256
#define HID 128
#define NCLS 32
#define NPRE 128

// ---------------- scratch ----------------
__device__ int   g_cnt[NN];
__device__ int   g_rowptr[NN];
__device__ int   g_cursor[NN];
__device__ int   g_part[NPRE];
__device__ float g_dinv[NN];
__device__ int   g_csr[NE];
__device__ int   g_is64;
__device__ int   g_ready = 0;
__device__ unsigned g_bar_cnt = 0;
__device__ volatile unsigned g_bar_gen = 0;
__device__ __align__(16) float  g_xw1[(size_t)NN * HID];
__device__ __align__(16) float  g_xw2[(size_t)NN * NCLS];
__device__ __align__(16) __half g_W1h[HID * FIN];   // W1^T fp16 [n][k]

// ---------------- helpers ----------------
__device__ __forceinline__ int load_idx(const void* p, long long i, int is64) {
    if (is64) return (int)((const long long*)p)[i];
    return ((const int*)p)[i];
}
__device__ __forceinline__ uint32_t smem_u32(const void* p) {
    uint32_t a;
    asm("{ .reg .u64 t; cvta.to.shared.u64 t, %1; cvt.u32.u64 %0, t; }" : "=r"(a) : "l"(p));
    return a;
}
__device__ __forceinline__ void ldsm4(uint4& r, uint32_t addr) {
    asm volatile("ldmatrix.sync.aligned.m8n8.x4.shared.b16 {%0,%1,%2,%3}, [%4];"
                 : "=r"(r.x), "=r"(r.y), "=r"(r.z), "=r"(r.w) : "r"(addr));
}
__device__ __forceinline__ void mma16816(float c[4], const uint4& a, uint32_t b0, uint32_t b1) {
    asm volatile(
        "mma.sync.aligned.m16n8k16.row.col.f32.f16.f16.f32 "
        "{%0,%1,%2,%3}, {%4,%5,%6,%7}, {%8,%9}, {%0,%1,%2,%3};"
        : "+f"(c[0]), "+f"(c[1]), "+f"(c[2]), "+f"(c[3])
        : "r"(a.x), "r"(a.y), "r"(a.z), "r"(a.w), "r"(b0), "r"(b1));
}
__device__ __forceinline__ uint32_t packh2(float a, float b) {
    __half2 h = __floats2half2_rn(a, b);
    return *(uint32_t*)&h;
}

__device__ __forceinline__ void pre_grid_bar() {
    __syncthreads();
    if (threadIdx.x == 0) {
        __threadfence();
        unsigned g = g_bar_gen;
        if (atomicAdd(&g_bar_cnt, 1u) == NPRE - 1) {
            g_bar_cnt = 0;
            __threadfence();
            g_bar_gen = g + 1;
        } else {
            while (g_bar_gen == g) { __nanosleep(64); }
        }
    }
    __syncthreads();
}

__device__ __forceinline__ int block_exscan(int v, int* p_total, int* wsum) {
    const int lane = threadIdx.x & 31, w = threadIdx.x >> 5;
    const int nw = blockDim.x >> 5;
    int x = v;
#pragma unroll
    for (int o = 1; o < 32; o <<= 1) {
        int y = __shfl_up_sync(0xffffffffu, x, o);
        if (lane >= o) x += y;
    }
    if (lane == 31) wsum[w] = x;
    __syncthreads();
    if (w == 0) {
        int s = (lane < nw) ? wsum[lane] : 0;
#pragma unroll
        for (int o = 1; o < 32; o <<= 1) {
            int y = __shfl_up_sync(0xffffffffu, s, o);
            if (lane >= o) s += y;
        }
        wsum[lane] = s;
    }
    __syncthreads();
    int base = (w > 0) ? wsum[w - 1] : 0;
    *p_total = wsum[31];
    __syncthreads();
    return base + (x - v);
}

// ================= FAT: preproc (blocks < NPRE) + fp16-MMA GEMM1 =================
// dyn smem: A[2][16KB] + B[2][16KB] = 64 KB. SW128 layout: row r (128B), chunk c at (c ^ (r&7))*16.
__global__ __launch_bounds__(256) void k_fat(const float* __restrict__ X,
                                             const float* __restrict__ W1,
                                             const void* __restrict__ ei,
                                             int n, int e) {
    extern __shared__ char dsm[];
    __shared__ int p_wsum[32];
    __shared__ int p_boff;
    const int tid = threadIdx.x;

    if (blockIdx.x < NPRE) {
        const int gt = blockIdx.x * 256 + tid;
        const int GT = NPRE * 256;
        // phase 0: zero counts, detect dtype, build W1h = W1^T fp16
        for (int i = gt; i < n; i += GT) g_cnt[i] = 0;
        for (int i = gt; i < HID * FIN; i += GT) {
            int nn2 = i >> 8, k = i & 255;
            g_W1h[i] = __float2half(W1[(size_t)k * HID + nn2]);
        }
        if (gt == 0) {
            const long long* p = (const long long*)ei;
            int ok = 1;
            for (int j = 0; j < 256; j++) {
                long long v = p[j];
                if (v < 0 || v >= n) { ok = 0; break; }
            }
            g_is64 = ok;
        }
        pre_grid_bar();
        if (blockIdx.x == 0 && tid == 0) *(volatile int*)&g_ready = 1;
        // phase 1: histogram
        const int is64 = g_is64;
        for (int i = gt; i < e; i += GT) {
            int d = load_idx(ei, (long long)e + i, is64);
            atomicAdd(&g_cnt[d], 1);
        }
        pre_grid_bar();
        // phase 2: scan
        const int L = (n + GT - 1) / GT;
        const int base = gt * L;
        const int end = (base + L < n) ? base + L : n;
        int s = 0;
        for (int i = base; i < end; i++) s += __ldcg(&g_cnt[i]);
        int tot;
        int ex = block_exscan(s, &tot, p_wsum);
        if (tid == 0) g_part[blockIdx.x] = tot;
        pre_grid_bar();
        {
            int v = (tid < NPRE) ? __ldcg(&g_part[tid]) : 0;
            int t2;
            int ex2 = block_exscan(v, &t2, p_wsum);
            if (tid == (int)blockIdx.x) p_boff = ex2;
            __syncthreads();
            int run = p_boff + ex;
            for (int i = base; i < end; i++) {
                int c = __ldcg(&g_cnt[i]);
                g_rowptr[i] = run;
                g_cursor[i] = run;
                g_dinv[i] = rsqrtf((float)(c + 1));
                run += c;
            }
        }
        pre_grid_bar();
        // phase 3: scatter
        for (int i = gt; i < e; i += GT) {
            int s0 = load_idx(ei, i, is64);
            int d0 = load_idx(ei, (long long)e + i, is64);
            int pos = atomicAdd(&g_cursor[d0], 1);
            g_csr[pos] = s0;
        }
        return;
    }

    // ---------------- GEMM1: 128x128 tile, BK=64, fp16 MMA ----------------
    while (*(volatile int*)&g_ready == 0) { __nanosleep(128); }
    __threadfence();

    const int bid = blockIdx.x - NPRE;
    const int row0 = bid * 128;
    const int lane = tid & 31, warp = tid >> 5;
    const int wm = warp & 3, wn = warp >> 2;   // 4 x 2 warp grid; warp tile 32 x 64
    const uint32_t sbase = smem_u32(dsm);
    const uint32_t sA[2] = { sbase, sbase + 16384 };
    const uint32_t sB[2] = { sbase + 32768, sbase + 49152 };

    float c[2][8][4];
#pragma unroll
    for (int i = 0; i < 2; i++)
#pragma unroll
        for (int j = 0; j < 8; j++)
#pragma unroll
            for (int v = 0; v < 4; v++) c[i][j][v] = 0.f;

    // loaders: thread -> row m = tid>>1, chunk base (tid&1)*4, 4 chunks of 8 elems
    const int lm = tid >> 1;
    const int lcb = (tid & 1) * 4;
    int arow = row0 + lm; if (arow >= n) arow = n - 1;
    const float4* ag = (const float4*)(X + (size_t)arow * FIN);
    const __half* bg = g_W1h + (size_t)lm * FIN;
    const uint32_t aw = sA[0] - sbase + lm * 128;  // relative row offsets identical for both buffers
    const int asw = lm & 7;

    float4 ra[8];
    uint4  rb[4];
#define G_LOAD(kt) do {                                              \
        _Pragma("unroll")                                            \
        for (int j = 0; j < 4; j++) {                                \
            ra[2*j]   = ag[(kt)*16 + (lcb + j)*2];                   \
            ra[2*j+1] = ag[(kt)*16 + (lcb + j)*2 + 1];               \
            rb[j] = *(const uint4*)(bg + (kt)*64 + (lcb + j)*8);     \
        }                                                            \
    } while (0)
#define G_STS(bi) do {                                               \
        _Pragma("unroll")                                            \
        for (int j = 0; j < 4; j++) {                                \
            int ph = ((lcb + j) ^ asw) * 16;                         \
            uint4 av = make_uint4(packh2(ra[2*j].x, ra[2*j].y),      \
                                  packh2(ra[2*j].z, ra[2*j].w),      \
                                  packh2(ra[2*j+1].x, ra[2*j+1].y),  \
                                  packh2(ra[2*j+1].z, ra[2*j+1].w)); \
            *(uint4*)(size_t)0;                                      \
        }                                                            \
    } while (0)
#undef G_STS
    // (store via shared-space pointers)
    char* dA[2] = { dsm, dsm + 16384 };
    char* dB[2] = { dsm + 32768, dsm + 49152 };
#define G_STS(bi) do {                                               \
        _Pragma("unroll")                                            \
        for (int j = 0; j < 4; j++) {                                \
            int ph = ((lcb + j) ^ asw) * 16;                         \
            uint4 av = make_uint4(packh2(ra[2*j].x, ra[2*j].y),      \
                                  packh2(ra[2*j].z, ra[2*j].w),      \
                                  packh2(ra[2*j+1].x, ra[2*j+1].y),  \
                                  packh2(ra[2*j+1].z, ra[2*j+1].w)); \
            *(uint4*)(dA[bi] + lm * 128 + ph) = av;                  \
            *(uint4*)(dB[bi] + lm * 128 + ph) = rb[j];               \
        }                                                            \
    } while (0)

    G_LOAD(0);
    G_STS(0);
    for (int kt = 0; kt < FIN / 64; kt++) {
        __syncthreads();
        if (kt + 1 < FIN / 64) G_LOAD(kt + 1);
        const int bi = kt & 1;
        const int lrow = (lane & 15) * 128;
        const int lhi = lane >> 4, lsw = lane & 7;
#pragma unroll
        for (int kp = 0; kp < 4; kp++) {
            uint4 af[2];
#pragma unroll
            for (int mt = 0; mt < 2; mt++)
                ldsm4(af[mt], sA[bi] + (wm * 32 + mt * 16) * 128 + lrow +
                               (((kp * 2 + lhi) ^ lsw) * 16));
            uint4 bf[4];
#pragma unroll
            for (int bt = 0; bt < 4; bt++)
                ldsm4(bf[bt], sB[bi] + (wn * 64 + bt * 16) * 128 + lrow +
                               (((kp * 2 + lhi) ^ lsw) * 16));
#pragma unroll
            for (int mt = 0; mt < 2; mt++)
#pragma unroll
                for (int bt = 0; bt < 4; bt++) {
                    mma16816(c[mt][2 * bt],     af[mt], bf[bt].x, bf[bt].z);
                    mma16816(c[mt][2 * bt + 1], af[mt], bf[bt].y, bf[bt].w);
                }
        }
        if (kt + 1 < FIN / 64) G_STS((kt + 1) & 1);
    }

    const int g = lane >> 2, cp = (lane & 3) * 2;
#pragma unroll
    for (int mt = 0; mt < 2; mt++) {
        int r1 = row0 + wm * 32 + mt * 16 + g;
        int r2 = r1 + 8;
#pragma unroll
        for (int nt = 0; nt < 8; nt++) {
            int col = wn * 64 + nt * 8 + cp;
            if (r1 < n) *(float2*)&g_xw1[(size_t)r1 * HID + col] =
                make_float2(c[mt][nt][0], c[mt][nt][1]);
            if (r2 < n) *(float2*)&g_xw1[(size_t)r2 * HID + col] =
                make_float2(c[mt][nt][2], c[mt][nt][3]);
        }
    }
}

// ---------------- Agg1 + GEMM2 fused: xw2 = (relu(Ahat@xw1 + b1)) @ W2 ----------------
__global__ __launch_bounds__(512) void k_agg1(const float* __restrict__ b1,
                                              const float* __restrict__ W2, int n) {
    __shared__ float W2s[HID * NCLS];   // 16 KB [k][c]
    __shared__ float hs[16][HID];       // 8 KB
    const int tid = threadIdx.x, lane = tid & 31, wid = tid >> 5;
    {
        const float4* src = (const float4*)W2;
        float4* dst = (float4*)W2s;
        for (int i = tid; i < HID * NCLS / 4; i += 512) dst[i] = src[i];
    }
    __syncthreads();

    int node = blockIdx.x * 16 + wid;
    if (node >= n) return;
    int start = g_rowptr[node];
    int cnt = g_cnt[node];
    float di = g_dinv[node];
    float4 v = ((const float4*)&g_xw1[(size_t)node * HID])[lane];
    float4 acc = make_float4(di * v.x, di * v.y, di * v.z, di * v.w);
    int t = 0;
    for (; t + 4 <= cnt; t += 4) {
        int s0 = g_csr[start + t],     s1 = g_csr[start + t + 1];
        int s2 = g_csr[start + t + 2], s3 = g_csr[start + t + 3];
        float d0 = g_dinv[s0], d1 = g_dinv[s1], d2 = g_dinv[s2], d3 = g_dinv[s3];
        float4 w0 = ((const float4*)&g_xw1[(size_t)s0 * HID])[lane];
        float4 w1 = ((const float4*)&g_xw1[(size_t)s1 * HID])[lane];
        float4 w2 = ((const float4*)&g_xw1[(size_t)s2 * HID])[lane];
        float4 w3 = ((const float4*)&g_xw1[(size_t)s3 * HID])[lane];
        acc.x += d0*w0.x + d1*w1.x + d2*w2.x + d3*w3.x;
        acc.y += d0*w0.y + d1*w1.y + d2*w2.y + d3*w3.y;
        acc.z += d0*w0.z + d1*w1.z + d2*w2.z + d3*w3.z;
        acc.w += d0*w0.w + d1*w1.w + d2*w2.w + d3*w3.w;
    }
    for (; t < cnt; t++) {
        int s0 = g_csr[start + t];
        float d0 = g_dinv[s0];
        float4 w0 = ((const float4*)&g_xw1[(size_t)s0 * HID])[lane];
        acc.x += d0 * w0.x; acc.y += d0 * w0.y; acc.z += d0 * w0.z; acc.w += d0 * w0.w;
    }
    float4 bb = ((const float4*)b1)[lane];
    float4 h;
    h.x = fmaxf(fmaf(di, acc.x, bb.x), 0.f);
    h.y = fmaxf(fmaf(di, acc.y, bb.y), 0.f);
    h.z = fmaxf(fmaf(di, acc.z, bb.z), 0.f);
    h.w = fmaxf(fmaf(di, acc.w, bb.w), 0.f);
    ((float4*)hs[wid])[lane] = h;
    __syncwarp();
    // xw2[node][lane] = sum_k h[k] * W2[k][lane]
    float out = 0.f;
    const float4* h4 = (const float4*)hs[wid];
#pragma unroll
    for (int kk = 0; kk < 32; kk++) {
        float4 hv = h4[kk];
        out = fmaf(hv.x, W2s[(kk * 4 + 0) * NCLS + lane], out);
        out = fmaf(hv.y, W2s[(kk * 4 + 1) * NCLS + lane], out);
        out = fmaf(hv.z, W2s[(kk * 4 + 2) * NCLS + lane], out);
        out = fmaf(hv.w, W2s[(kk * 4 + 3) * NCLS + lane], out);
    }
    g_xw2[(size_t)node * NCLS + lane] = out;
}

// ---------------- Agg2 + log_softmax: 4 edges/warp in parallel ----------------
__global__ __launch_bounds__(256) void k_agg2(const float* __restrict__ b2,
                                              float* __restrict__ out, int n) {
    const int tid = threadIdx.x, lane = tid & 31;
    const int grp = lane >> 3, li = lane & 7;
    int node = blockIdx.x * 8 + (tid >> 5);
    if (node >= n) return;
    int start = g_rowptr[node];
    int cnt = g_cnt[node];
    float di = g_dinv[node];
    float4 acc = make_float4(0.f, 0.f, 0.f, 0.f);
    if (grp == 0) {
        float4 s = ((const float4*)&g_xw2[(size_t)node * NCLS])[li];
        acc = make_float4(di * s.x, di * s.y, di * s.z, di * s.w);
    }
    for (int t = grp; t < cnt; t += 4) {
        int s = g_csr[start + t];
        float ds = g_dinv[s];
        float4 w = ((const float4*)&g_xw2[(size_t)s * NCLS])[li];
        acc.x = fmaf(ds, w.x, acc.x);
        acc.y = fmaf(ds, w.y, acc.y);
        acc.z = fmaf(ds, w.z, acc.z);
        acc.w = fmaf(ds, w.w, acc.w);
    }
#pragma unroll
    for (int o = 8; o <= 16; o <<= 1) {
        acc.x += __shfl_xor_sync(0xffffffffu, acc.x, o);
        acc.y += __shfl_xor_sync(0xffffffffu, acc.y, o);
        acc.z += __shfl_xor_sync(0xffffffffu, acc.z, o);
        acc.w += __shfl_xor_sync(0xffffffffu, acc.w, o);
    }
    float4 bb = ((const float4*)b2)[li];
    float4 vv = make_float4(fmaf(di, acc.x, bb.x), fmaf(di, acc.y, bb.y),
                            fmaf(di, acc.z, bb.z), fmaf(di, acc.w, bb.w));
    float m = fmaxf(fmaxf(vv.x, vv.y), fmaxf(vv.z, vv.w));
#pragma unroll
    for (int o = 1; o <= 4; o <<= 1) m = fmaxf(m, __shfl_xor_sync(0xffffffffu, m, o));
    float s4 = __expf(vv.x - m) + __expf(vv.y - m) + __expf(vv.z - m) + __expf(vv.w - m);
#pragma unroll
    for (int o = 1; o <= 4; o <<= 1) s4 += __shfl_xor_sync(0xffffffffu, s4, o);
    float ls = m + logf(s4);
    if (lane < 8)
        ((float4*)&out[(size_t)node * NCLS])[li] =
            make_float4(vv.x - ls, vv.y - ls, vv.z - ls, vv.w - ls);
}

// ---------------- launch ----------------
extern "C" void kernel_launch(void* const* d_in, const int* in_sizes, int n_in,
                              void* d_out, int out_size) {
    const float* X = (const float*)d_in[0];
    const void* EI = d_in[1];
    const float* W1 = (const float*)d_in[2];
    const float* b1 = (const float*)d_in[3];
    const float* W2 = (const float*)d_in[4];
    const float* b2 = (const float*)d_in[5];
    float* out = (float*)d_out;

    int n = in_sizes[0] / FIN;   // 100000
    int e = in_sizes[1] / 2;     // 800000

    static int smem_set = 0;
    if (!smem_set) {
        cudaFuncSetAttribute(k_fat, cudaFuncAttributeMaxDynamicSharedMemorySize, 65536);
        smem_set = 1;
    }

    int g1blocks = (n + 127) / 128;  // 782
    k_fat<<<NPRE + g1blocks, 256, 65536>>>(X, W1, EI, n, e);
    k_agg1<<<(n + 15) / 16, 512>>>(b1, W2, n);
    k_agg2<<<(n + 7) / 8, 256>>>(b2, out, n);
}

// round 8
// speedup vs baseline: 1.9415x; 1.3909x over previous
#include <cuda_runtime.h>
#include <cuda_fp16.h>
#include <cstdint>

#define NN 100000
#define NE 800000
#define FIN 256
#define HID 128
#define NCLS 32
#define NPRE 128

// ---------------- scratch ----------------
__device__ int   g_cnt[NN];
__device__ int   g_rowptr[NN];
__device__ int   g_cursor[NN];
__device__ int   g_part[NPRE];
__device__ float g_dinv[NN];
__device__ int   g_csr[NE];
__device__ int   g_is64;
__device__ int   g_ready = 0;
__device__ unsigned g_bar_cnt = 0;
__device__ volatile unsigned g_bar_gen = 0;
__device__ __align__(16) __half g_xw1h[(size_t)NN * HID];  // X@W1, fp16
__device__ __align__(16) __half g_hh[(size_t)NN * HID];    // relu(agg1), fp16
__device__ __align__(16) float  g_xw2[(size_t)NN * NCLS];  // h@W2, f32
__device__ __align__(16) __half g_W1h[HID * FIN];          // W1^T fp16 [n][k]

// ---------------- helpers ----------------
__device__ __forceinline__ int load_idx(const void* p, long long i, int is64) {
    if (is64) return (int)((const long long*)p)[i];
    return ((const int*)p)[i];
}
__device__ __forceinline__ uint32_t smem_u32(const void* p) {
    uint32_t a;
    asm("{ .reg .u64 t; cvta.to.shared.u64 t, %1; cvt.u32.u64 %0, t; }" : "=r"(a) : "l"(p));
    return a;
}
__device__ __forceinline__ void ldsm4(uint4& r, uint32_t addr) {
    asm volatile("ldmatrix.sync.aligned.m8n8.x4.shared.b16 {%0,%1,%2,%3}, [%4];"
                 : "=r"(r.x), "=r"(r.y), "=r"(r.z), "=r"(r.w) : "r"(addr));
}
__device__ __forceinline__ void mma16816(float c[4], const uint4& a, uint32_t b0, uint32_t b1) {
    asm volatile(
        "mma.sync.aligned.m16n8k16.row.col.f32.f16.f16.f32 "
        "{%0,%1,%2,%3}, {%4,%5,%6,%7}, {%8,%9}, {%0,%1,%2,%3};"
        : "+f"(c[0]), "+f"(c[1]), "+f"(c[2]), "+f"(c[3])
        : "r"(a.x), "r"(a.y), "r"(a.z), "r"(a.w), "r"(b0), "r"(b1));
}
__device__ __forceinline__ uint32_t packh2(float a, float b) {
    __half2 h = __floats2half2_rn(a, b);
    return *(uint32_t*)&h;
}

__device__ __forceinline__ void pre_grid_bar() {
    __syncthreads();
    if (threadIdx.x == 0) {
        __threadfence();
        unsigned g = g_bar_gen;
        if (atomicAdd(&g_bar_cnt, 1u) == NPRE - 1) {
            g_bar_cnt = 0;
            __threadfence();
            g_bar_gen = g + 1;
        } else {
            while (g_bar_gen == g) { __nanosleep(64); }
        }
    }
    __syncthreads();
}

__device__ __forceinline__ int block_exscan(int v, int* p_total, int* wsum) {
    const int lane = threadIdx.x & 31, w = threadIdx.x >> 5;
    const int nw = blockDim.x >> 5;
    int x = v;
#pragma unroll
    for (int o = 1; o < 32; o <<= 1) {
        int y = __shfl_up_sync(0xffffffffu, x, o);
        if (lane >= o) x += y;
    }
    if (lane == 31) wsum[w] = x;
    __syncthreads();
    if (w == 0) {
        int s = (lane < nw) ? wsum[lane] : 0;
#pragma unroll
        for (int o = 1; o < 32; o <<= 1) {
            int y = __shfl_up_sync(0xffffffffu, s, o);
            if (lane >= o) s += y;
        }
        wsum[lane] = s;
    }
    __syncthreads();
    int base = (w > 0) ? wsum[w - 1] : 0;
    *p_total = wsum[31];
    __syncthreads();
    return base + (x - v);
}

// ================= FAT: preproc (blocks < NPRE) + fp16-MMA GEMM1, 512 threads =================
__global__ __launch_bounds__(512) void k_fat(const float* __restrict__ X,
                                             const float* __restrict__ W1,
                                             const void* __restrict__ ei,
                                             int n, int e) {
    extern __shared__ char dsm[];
    __shared__ int p_wsum[32];
    __shared__ int p_boff;
    const int tid = threadIdx.x;

    if (blockIdx.x < NPRE) {
        const int gt = blockIdx.x * 512 + tid;
        const int GT = NPRE * 512;
        for (int i = gt; i < n; i += GT) g_cnt[i] = 0;
        for (int i = gt; i < HID * FIN; i += GT) {
            int nn2 = i >> 8, k = i & 255;
            g_W1h[i] = __float2half(W1[(size_t)k * HID + nn2]);
        }
        if (gt == 0) {
            const long long* p = (const long long*)ei;
            int ok = 1;
            for (int j = 0; j < 256; j++) {
                long long v = p[j];
                if (v < 0 || v >= n) { ok = 0; break; }
            }
            g_is64 = ok;
        }
        pre_grid_bar();
        if (blockIdx.x == 0 && tid == 0) *(volatile int*)&g_ready = 1;
        const int is64 = g_is64;
        for (int i = gt; i < e; i += GT) {
            int d = load_idx(ei, (long long)e + i, is64);
            atomicAdd(&g_cnt[d], 1);
        }
        pre_grid_bar();
        const int L = (n + GT - 1) / GT;
        const int base = gt * L;
        const int end = (base + L < n) ? base + L : n;
        int s = 0;
        for (int i = base; i < end; i++) s += __ldcg(&g_cnt[i]);
        int tot;
        int ex = block_exscan(s, &tot, p_wsum);
        if (tid == 0) g_part[blockIdx.x] = tot;
        pre_grid_bar();
        {
            int v = (tid < NPRE) ? __ldcg(&g_part[tid]) : 0;
            int t2;
            int ex2 = block_exscan(v, &t2, p_wsum);
            if (tid == (int)blockIdx.x) p_boff = ex2;
            __syncthreads();
            int run = p_boff + ex;
            for (int i = base; i < end; i++) {
                int c = __ldcg(&g_cnt[i]);
                g_rowptr[i] = run;
                g_cursor[i] = run;
                g_dinv[i] = rsqrtf((float)(c + 1));
                run += c;
            }
        }
        pre_grid_bar();
        for (int i = gt; i < e; i += GT) {
            int s0 = load_idx(ei, i, is64);
            int d0 = load_idx(ei, (long long)e + i, is64);
            int pos = atomicAdd(&g_cursor[d0], 1);
            g_csr[pos] = s0;
        }
        return;
    }

    // -------- GEMM1: 128x128 tile, BK=64, warp grid 4x4 (warp tile 32x32) --------
    while (*(volatile int*)&g_ready == 0) { __nanosleep(128); }
    __threadfence();

    const int bid = blockIdx.x - NPRE;
    const int row0 = bid * 128;
    const int lane = tid & 31, warp = tid >> 5;
    const int wm = warp & 3, wn = warp >> 2;
    const uint32_t sbase = smem_u32(dsm);
    const uint32_t sA[2] = { sbase, sbase + 16384 };
    const uint32_t sB[2] = { sbase + 32768, sbase + 49152 };
    char* dA[2] = { dsm, dsm + 16384 };
    char* dB[2] = { dsm + 32768, dsm + 49152 };

    float c[2][4][4];
#pragma unroll
    for (int i = 0; i < 2; i++)
#pragma unroll
        for (int j = 0; j < 4; j++)
#pragma unroll
            for (int v = 0; v < 4; v++) c[i][j][v] = 0.f;

    // loaders: thread -> row lm = tid>>2 (0..127), chunks lc0, lc0+1 (of 8 16B-chunks)
    const int lm = tid >> 2;
    const int lc0 = (tid & 3) * 2;
    const int asw = lm & 7;
    int arow = row0 + lm; if (arow >= n) arow = n - 1;
    const float* ag = X + (size_t)arow * FIN;
    const __half* bg = g_W1h + (size_t)lm * FIN;

    float4 ra[4];
    uint4  rb[2];
#define G_LOAD(kt) do {                                                \
        _Pragma("unroll")                                              \
        for (int j = 0; j < 2; j++) {                                  \
            int cc = lc0 + j;                                          \
            ra[2*j]   = *(const float4*)(ag + (kt)*64 + cc*8);         \
            ra[2*j+1] = *(const float4*)(ag + (kt)*64 + cc*8 + 4);     \
            rb[j]     = *(const uint4*)(bg + (kt)*64 + cc*8);          \
        }                                                              \
    } while (0)
#define G_STS(bi) do {                                                 \
        _Pragma("unroll")                                              \
        for (int j = 0; j < 2; j++) {                                  \
            int cc = lc0 + j;                                          \
            int ph = ((cc ^ asw)) * 16;                                \
            uint4 av = make_uint4(packh2(ra[2*j].x, ra[2*j].y),        \
                                  packh2(ra[2*j].z, ra[2*j].w),        \
                                  packh2(ra[2*j+1].x, ra[2*j+1].y),    \
                                  packh2(ra[2*j+1].z, ra[2*j+1].w));   \
            *(uint4*)(dA[bi] + lm * 128 + ph) = av;                    \
            *(uint4*)(dB[bi] + lm * 128 + ph) = rb[j];                 \
        }                                                              \
    } while (0)

    G_LOAD(0);
    G_STS(0);
    const int lr = lane & 15, lhi = lane >> 4, lsw = lane & 7;
    for (int kt = 0; kt < FIN / 64; kt++) {
        __syncthreads();
        if (kt + 1 < FIN / 64) G_LOAD(kt + 1);
        const int bi = kt & 1;
#pragma unroll
        for (int kp = 0; kp < 4; kp++) {
            const int ch = ((kp * 2 + lhi) ^ lsw) * 16;
            uint4 af[2];
#pragma unroll
            for (int mt = 0; mt < 2; mt++)
                ldsm4(af[mt], sA[bi] + (wm * 32 + mt * 16 + lr) * 128 + ch);
            uint4 bf[2];
#pragma unroll
            for (int bt = 0; bt < 2; bt++)
                ldsm4(bf[bt], sB[bi] + (wn * 32 + bt * 16 + lr) * 128 + ch);
#pragma unroll
            for (int mt = 0; mt < 2; mt++)
#pragma unroll
                for (int bt = 0; bt < 2; bt++) {
                    mma16816(c[mt][2 * bt],     af[mt], bf[bt].x, bf[bt].z);
                    mma16816(c[mt][2 * bt + 1], af[mt], bf[bt].y, bf[bt].w);
                }
        }
        if (kt + 1 < FIN / 64) G_STS((kt + 1) & 1);
    }

    const int g = lane >> 2, cp = (lane & 3) * 2;
#pragma unroll
    for (int mt = 0; mt < 2; mt++) {
        int r1 = row0 + wm * 32 + mt * 16 + g;
        int r2 = r1 + 8;
#pragma unroll
        for (int nt = 0; nt < 4; nt++) {
            int col = wn * 32 + nt * 8 + cp;
            if (r1 < n) {
                __half2 h = __floats2half2_rn(c[mt][nt][0], c[mt][nt][1]);
                *(__half2*)&g_xw1h[(size_t)r1 * HID + col] = h;
            }
            if (r2 < n) {
                __half2 h = __floats2half2_rn(c[mt][nt][2], c[mt][nt][3]);
                *(__half2*)&g_xw1h[(size_t)r2 * HID + col] = h;
            }
        }
    }
}

// ---------------- Agg1: h = relu(Ahat @ xw1 + b1), warp/node, fp16 gathers ----------------
__global__ __launch_bounds__(256) void k_agg1(const float* __restrict__ b1, int n) {
    int node = blockIdx.x * 8 + (threadIdx.x >> 5);
    int lane = threadIdx.x & 31;
    if (node >= n) return;
    int start = g_rowptr[node];
    int cnt = g_cnt[node];
    float di = g_dinv[node];
    uint2 sv = ((const uint2*)&g_xw1h[(size_t)node * HID])[lane];
    float2 s0 = __half22float2(*(__half2*)&sv.x);
    float2 s1 = __half22float2(*(__half2*)&sv.y);
    float4 acc = make_float4(di * s0.x, di * s0.y, di * s1.x, di * s1.y);
    int t = 0;
    for (; t + 4 <= cnt; t += 4) {
        int e0 = g_csr[start + t],     e1 = g_csr[start + t + 1];
        int e2 = g_csr[start + t + 2], e3 = g_csr[start + t + 3];
        float d0 = g_dinv[e0], d1 = g_dinv[e1], d2 = g_dinv[e2], d3 = g_dinv[e3];
        uint2 w0 = ((const uint2*)&g_xw1h[(size_t)e0 * HID])[lane];
        uint2 w1 = ((const uint2*)&g_xw1h[(size_t)e1 * HID])[lane];
        uint2 w2 = ((const uint2*)&g_xw1h[(size_t)e2 * HID])[lane];
        uint2 w3 = ((const uint2*)&g_xw1h[(size_t)e3 * HID])[lane];
        float2 a0 = __half22float2(*(__half2*)&w0.x), b0 = __half22float2(*(__half2*)&w0.y);
        float2 a1 = __half22float2(*(__half2*)&w1.x), b1v = __half22float2(*(__half2*)&w1.y);
        float2 a2 = __half22float2(*(__half2*)&w2.x), b2v = __half22float2(*(__half2*)&w2.y);
        float2 a3 = __half22float2(*(__half2*)&w3.x), b3v = __half22float2(*(__half2*)&w3.y);
        acc.x += d0*a0.x + d1*a1.x + d2*a2.x + d3*a3.x;
        acc.y += d0*a0.y + d1*a1.y + d2*a2.y + d3*a3.y;
        acc.z += d0*b0.x + d1*b1v.x + d2*b2v.x + d3*b3v.x;
        acc.w += d0*b0.y + d1*b1v.y + d2*b2v.y + d3*b3v.y;
    }
    for (; t < cnt; t++) {
        int e0 = g_csr[start + t];
        float d0 = g_dinv[e0];
        uint2 w0 = ((const uint2*)&g_xw1h[(size_t)e0 * HID])[lane];
        float2 a0 = __half22float2(*(__half2*)&w0.x), b0 = __half22float2(*(__half2*)&w0.y);
        acc.x += d0 * a0.x; acc.y += d0 * a0.y; acc.z += d0 * b0.x; acc.w += d0 * b0.y;
    }
    float4 bb = ((const float4*)b1)[lane];
    float hx = fmaxf(fmaf(di, acc.x, bb.x), 0.f);
    float hy = fmaxf(fmaf(di, acc.y, bb.y), 0.f);
    float hz = fmaxf(fmaf(di, acc.z, bb.z), 0.f);
    float hw = fmaxf(fmaf(di, acc.w, bb.w), 0.f);
    uint2 o;
    o.x = packh2(hx, hy);
    o.y = packh2(hz, hw);
    ((uint2*)&g_hh[(size_t)node * HID])[lane] = o;
}

// ---------------- GEMM2: xw2 = h[100k,128] @ W2[128,32], fp16 MMA, single K pass ----------------
__global__ __launch_bounds__(256) void k_gemm2(const float* __restrict__ W2, int n) {
    __shared__ __align__(16) __half As[128 * 128];  // 32 KB, 256B rows, 16 chunks swizzled
    __shared__ __align__(16) __half Bs[32 * 128];   // 8 KB
    const int tid = threadIdx.x, lane = tid & 31, warp = tid >> 5;
    const int row0 = blockIdx.x * 128;
    const uint32_t sA = smem_u32(As), sB = smem_u32(Bs);

    // load A (h fp16): thread -> row lm = tid>>1, chunks (tid&1)*8 + j
    {
        const int lm = tid >> 1;
        int arow = row0 + lm; if (arow >= n) arow = n - 1;
        const uint4* src = (const uint4*)&g_hh[(size_t)arow * HID];
#pragma unroll
        for (int j = 0; j < 8; j++) {
            int cc = (tid & 1) * 8 + j;
            *(uint4*)((char*)As + lm * 256 + ((cc ^ (lm & 7)) * 16)) = src[cc];
        }
    }
    // load B = W2^T fp16: thread -> class nn = tid>>3, k-chunk pair
    {
        const int nn2 = tid >> 3;           // 0..31
        const int kc = (tid & 7) * 16;      // 0..112
        __half tmp[16];
#pragma unroll
        for (int k = 0; k < 16; k++) tmp[k] = __float2half(W2[(size_t)(kc + k) * NCLS + nn2]);
#pragma unroll
        for (int j = 0; j < 2; j++) {
            int cc = kc / 8 + j;
            *(uint4*)((char*)Bs + nn2 * 256 + ((cc ^ (nn2 & 7)) * 16)) = *(uint4*)&tmp[j * 8];
        }
    }
    __syncthreads();

    float c[4][4];
#pragma unroll
    for (int j = 0; j < 4; j++)
#pragma unroll
        for (int v = 0; v < 4; v++) c[j][v] = 0.f;

    const int lr = lane & 15, lhi = lane >> 4, lsw = lane & 7;
#pragma unroll
    for (int kp = 0; kp < 8; kp++) {
        const int ch = ((kp * 2 + lhi) ^ lsw) * 16;
        uint4 af;
        ldsm4(af, sA + (warp * 16 + lr) * 256 + ch);
        uint4 bf[2];
#pragma unroll
        for (int bt = 0; bt < 2; bt++)
            ldsm4(bf[bt], sB + (bt * 16 + lr) * 256 + ch);
#pragma unroll
        for (int bt = 0; bt < 2; bt++) {
            mma16816(c[2 * bt],     af, bf[bt].x, bf[bt].z);
            mma16816(c[2 * bt + 1], af, bf[bt].y, bf[bt].w);
        }
    }

    const int g = lane >> 2, cp = (lane & 3) * 2;
    int r1 = row0 + warp * 16 + g;
    int r2 = r1 + 8;
#pragma unroll
    for (int nt = 0; nt < 4; nt++) {
        int col = nt * 8 + cp;
        if (r1 < n) *(float2*)&g_xw2[(size_t)r1 * NCLS + col] = make_float2(c[nt][0], c[nt][1]);
        if (r2 < n) *(float2*)&g_xw2[(size_t)r2 * NCLS + col] = make_float2(c[nt][2], c[nt][3]);
    }
}

// ---------------- Agg2 + log_softmax: 4 edges/warp in parallel ----------------
__global__ __launch_bounds__(256) void k_agg2(const float* __restrict__ b2,
                                              float* __restrict__ out, int n) {
    const int tid = threadIdx.x, lane = tid & 31;
    const int grp = lane >> 3, li = lane & 7;
    int node = blockIdx.x * 8 + (tid >> 5);
    if (node >= n) return;
    int start = g_rowptr[node];
    int cnt = g_cnt[node];
    float di = g_dinv[node];
    float4 acc = make_float4(0.f, 0.f, 0.f, 0.f);
    if (grp == 0) {
        float4 s = ((const float4*)&g_xw2[(size_t)node * NCLS])[li];
        acc = make_float4(di * s.x, di * s.y, di * s.z, di * s.w);
    }
    for (int t = grp; t < cnt; t += 4) {
        int s = g_csr[start + t];
        float ds = g_dinv[s];
        float4 w = ((const float4*)&g_xw2[(size_t)s * NCLS])[li];
        acc.x = fmaf(ds, w.x, acc.x);
        acc.y = fmaf(ds, w.y, acc.y);
        acc.z = fmaf(ds, w.z, acc.z);
        acc.w = fmaf(ds, w.w, acc.w);
    }
#pragma unroll
    for (int o = 8; o <= 16; o <<= 1) {
        acc.x += __shfl_xor_sync(0xffffffffu, acc.x, o);
        acc.y += __shfl_xor_sync(0xffffffffu, acc.y, o);
        acc.z += __shfl_xor_sync(0xffffffffu, acc.z, o);
        acc.w += __shfl_xor_sync(0xffffffffu, acc.w, o);
    }
    float4 bb = ((const float4*)b2)[li];
    float4 vv = make_float4(fmaf(di, acc.x, bb.x), fmaf(di, acc.y, bb.y),
                            fmaf(di, acc.z, bb.z), fmaf(di, acc.w, bb.w));
    float m = fmaxf(fmaxf(vv.x, vv.y), fmaxf(vv.z, vv.w));
#pragma unroll
    for (int o = 1; o <= 4; o <<= 1) m = fmaxf(m, __shfl_xor_sync(0xffffffffu, m, o));
    float s4 = __expf(vv.x - m) + __expf(vv.y - m) + __expf(vv.z - m) + __expf(vv.w - m);
#pragma unroll
    for (int o = 1; o <= 4; o <<= 1) s4 += __shfl_xor_sync(0xffffffffu, s4, o);
    float ls = m + logf(s4);
    if (lane < 8)
        ((float4*)&out[(size_t)node * NCLS])[li] =
            make_float4(vv.x - ls, vv.y - ls, vv.z - ls, vv.w - ls);
}

// ---------------- launch ----------------
extern "C" void kernel_launch(void* const* d_in, const int* in_sizes, int n_in,
                              void* d_out, int out_size) {
    const float* X = (const float*)d_in[0];
    const void* EI = d_in[1];
    const float* W1 = (const float*)d_in[2];
    const float* b1 = (const float*)d_in[3];
    const float* W2 = (const float*)d_in[4];
    const float* b2 = (const float*)d_in[5];
    float* out = (float*)d_out;

    int n = in_sizes[0] / FIN;   // 100000
    int e = in_sizes[1] / 2;     // 800000

    static int smem_set = 0;
    if (!smem_set) {
        cudaFuncSetAttribute(k_fat, cudaFuncAttributeMaxDynamicSharedMemorySize, 65536);
        smem_set = 1;
    }

    int g1blocks = (n + 127) / 128;  // 782
    k_fat<<<NPRE + g1blocks, 512, 65536>>>(X, W1, EI, n, e);
    k_agg1<<<(n + 7) / 8, 256>>>(b1, n);
    k_gemm2<<<(n + 127) / 128, 256>>>(W2, n);
    k_agg2<<<(n + 7) / 8, 256>>>(b2, out, n);
}

// round 9
// speedup vs baseline: 2.0699x; 1.0661x over previous
#include <cuda_runtime.h>
#include <cuda_fp16.h>
#include <cstdint>

#define NN 100000
#define NE 800000
#define FIN 256
#define HID 128
#define NCLS 32
#define NPRE 128

// ---------------- scratch ----------------
__device__ int   g_cnt[NN];
__device__ int   g_rowptr[NN];
__device__ int   g_cursor[NN];
__device__ int   g_part[NPRE];
__device__ float g_dinv[NN];
__device__ int   g_csr[NE];
__device__ int   g_is64;
__device__ int   g_ready = 0;
__device__ int   g_ready2 = 0;
__device__ unsigned g_bar_cnt = 0;
__device__ volatile unsigned g_bar_gen = 0;
__device__ __align__(16) __half g_y1h[(size_t)NN * HID];   // dinv * (X@W1), fp16
__device__ __align__(16) float  g_y2[(size_t)NN * NCLS];   // dinv * (h@W2), f32
__device__ __align__(16) __half g_W1h[HID * FIN];          // W1^T fp16 [n][k]

// ---------------- helpers ----------------
__device__ __forceinline__ int load_idx(const void* p, long long i, int is64) {
    if (is64) return (int)((const long long*)p)[i];
    return ((const int*)p)[i];
}
__device__ __forceinline__ uint32_t smem_u32(const void* p) {
    uint32_t a;
    asm("{ .reg .u64 t; cvta.to.shared.u64 t, %1; cvt.u32.u64 %0, t; }" : "=r"(a) : "l"(p));
    return a;
}
__device__ __forceinline__ void ldsm4(uint4& r, uint32_t addr) {
    asm volatile("ldmatrix.sync.aligned.m8n8.x4.shared.b16 {%0,%1,%2,%3}, [%4];"
                 : "=r"(r.x), "=r"(r.y), "=r"(r.z), "=r"(r.w) : "r"(addr));
}
__device__ __forceinline__ void mma16816(float c[4], const uint4& a, uint32_t b0, uint32_t b1) {
    asm volatile(
        "mma.sync.aligned.m16n8k16.row.col.f32.f16.f16.f32 "
        "{%0,%1,%2,%3}, {%4,%5,%6,%7}, {%8,%9}, {%0,%1,%2,%3};"
        : "+f"(c[0]), "+f"(c[1]), "+f"(c[2]), "+f"(c[3])
        : "r"(a.x), "r"(a.y), "r"(a.z), "r"(a.w), "r"(b0), "r"(b1));
}
__device__ __forceinline__ uint32_t packh2(float a, float b) {
    __half2 h = __floats2half2_rn(a, b);
    return *(uint32_t*)&h;
}

__device__ __forceinline__ void pre_grid_bar() {
    __syncthreads();
    if (threadIdx.x == 0) {
        __threadfence();
        unsigned g = g_bar_gen;
        if (atomicAdd(&g_bar_cnt, 1u) == NPRE - 1) {
            g_bar_cnt = 0;
            __threadfence();
            g_bar_gen = g + 1;
        } else {
            while (g_bar_gen == g) { __nanosleep(64); }
        }
    }
    __syncthreads();
}

__device__ __forceinline__ int block_exscan(int v, int* p_total, int* wsum) {
    const int lane = threadIdx.x & 31, w = threadIdx.x >> 5;
    const int nw = blockDim.x >> 5;
    int x = v;
#pragma unroll
    for (int o = 1; o < 32; o <<= 1) {
        int y = __shfl_up_sync(0xffffffffu, x, o);
        if (lane >= o) x += y;
    }
    if (lane == 31) wsum[w] = x;
    __syncthreads();
    if (w == 0) {
        int s = (lane < nw) ? wsum[lane] : 0;
#pragma unroll
        for (int o = 1; o < 32; o <<= 1) {
            int y = __shfl_up_sync(0xffffffffu, s, o);
            if (lane >= o) s += y;
        }
        wsum[lane] = s;
    }
    __syncthreads();
    int base = (w > 0) ? wsum[w - 1] : 0;
    *p_total = wsum[31];
    __syncthreads();
    return base + (x - v);
}

// ================= FAT: preproc (blocks < NPRE) + fp16-MMA GEMM1, 512 threads =================
__global__ __launch_bounds__(512) void k_fat(const float* __restrict__ X,
                                             const float* __restrict__ W1,
                                             const void* __restrict__ ei,
                                             int n, int e) {
    extern __shared__ char dsm[];
    __shared__ int p_wsum[32];
    __shared__ int p_boff;
    const int tid = threadIdx.x;

    if (blockIdx.x < NPRE) {
        const int gt = blockIdx.x * 512 + tid;
        const int GT = NPRE * 512;
        for (int i = gt; i < n; i += GT) g_cnt[i] = 0;
        for (int i = gt; i < HID * FIN; i += GT) {
            int nn2 = i >> 8, k = i & 255;
            g_W1h[i] = __float2half(W1[(size_t)k * HID + nn2]);
        }
        if (gt == 0) {
            const long long* p = (const long long*)ei;
            int ok = 1;
            for (int j = 0; j < 256; j++) {
                long long v = p[j];
                if (v < 0 || v >= n) { ok = 0; break; }
            }
            g_is64 = ok;
        }
        pre_grid_bar();
        if (blockIdx.x == 0 && tid == 0) *(volatile int*)&g_ready = 1;
        const int is64 = g_is64;
        for (int i = gt; i < e; i += GT) {
            int d = load_idx(ei, (long long)e + i, is64);
            atomicAdd(&g_cnt[d], 1);
        }
        pre_grid_bar();
        const int L = (n + GT - 1) / GT;
        const int base = gt * L;
        const int end = (base + L < n) ? base + L : n;
        int s = 0;
        for (int i = base; i < end; i++) s += __ldcg(&g_cnt[i]);
        int tot;
        int ex = block_exscan(s, &tot, p_wsum);
        if (tid == 0) g_part[blockIdx.x] = tot;
        pre_grid_bar();
        {
            int v = (tid < NPRE) ? __ldcg(&g_part[tid]) : 0;
            int t2;
            int ex2 = block_exscan(v, &t2, p_wsum);
            if (tid == (int)blockIdx.x) p_boff = ex2;
            __syncthreads();
            int run = p_boff + ex;
            for (int i = base; i < end; i++) {
                int c = __ldcg(&g_cnt[i]);
                g_rowptr[i] = run;
                g_cursor[i] = run;
                g_dinv[i] = rsqrtf((float)(c + 1));
                run += c;
            }
        }
        pre_grid_bar();
        if (blockIdx.x == 0 && tid == 0) *(volatile int*)&g_ready2 = 1;  // dinv ready
        for (int i = gt; i < e; i += GT) {
            int s0 = load_idx(ei, i, is64);
            int d0 = load_idx(ei, (long long)e + i, is64);
            int pos = atomicAdd(&g_cursor[d0], 1);
            g_csr[pos] = s0;
        }
        return;
    }

    // -------- GEMM1: 128x128 tile, BK=64, warp grid 4x4 (warp tile 32x32) --------
    while (*(volatile int*)&g_ready == 0) { __nanosleep(128); }
    __threadfence();

    const int bid = blockIdx.x - NPRE;
    const int row0 = bid * 128;
    const int lane = tid & 31, warp = tid >> 5;
    const int wm = warp & 3, wn = warp >> 2;
    const uint32_t sbase = smem_u32(dsm);
    const uint32_t sA[2] = { sbase, sbase + 16384 };
    const uint32_t sB[2] = { sbase + 32768, sbase + 49152 };
    char* dA[2] = { dsm, dsm + 16384 };
    char* dB[2] = { dsm + 32768, dsm + 49152 };

    float c[2][4][4];
#pragma unroll
    for (int i = 0; i < 2; i++)
#pragma unroll
        for (int j = 0; j < 4; j++)
#pragma unroll
            for (int v = 0; v < 4; v++) c[i][j][v] = 0.f;

    const int lm = tid >> 2;
    const int lc0 = (tid & 3) * 2;
    const int asw = lm & 7;
    int arow = row0 + lm; if (arow >= n) arow = n - 1;
    const float* ag = X + (size_t)arow * FIN;
    const __half* bg = g_W1h + (size_t)lm * FIN;

    float4 ra[4];
    uint4  rb[2];
#define G_LOAD(kt) do {                                                \
        _Pragma("unroll")                                              \
        for (int j = 0; j < 2; j++) {                                  \
            int cc = lc0 + j;                                          \
            ra[2*j]   = *(const float4*)(ag + (kt)*64 + cc*8);         \
            ra[2*j+1] = *(const float4*)(ag + (kt)*64 + cc*8 + 4);     \
            rb[j]     = *(const uint4*)(bg + (kt)*64 + cc*8);          \
        }                                                              \
    } while (0)
#define G_STS(bi) do {                                                 \
        _Pragma("unroll")                                              \
        for (int j = 0; j < 2; j++) {                                  \
            int cc = lc0 + j;                                          \
            int ph = ((cc ^ asw)) * 16;                                \
            uint4 av = make_uint4(packh2(ra[2*j].x, ra[2*j].y),        \
                                  packh2(ra[2*j].z, ra[2*j].w),        \
                                  packh2(ra[2*j+1].x, ra[2*j+1].y),    \
                                  packh2(ra[2*j+1].z, ra[2*j+1].w));   \
            *(uint4*)(dA[bi] + lm * 128 + ph) = av;                    \
            *(uint4*)(dB[bi] + lm * 128 + ph) = rb[j];                 \
        }                                                              \
    } while (0)

    G_LOAD(0);
    G_STS(0);
    const int lr = lane & 15, lhi = lane >> 4, lsw = lane & 7;
    for (int kt = 0; kt < FIN / 64; kt++) {
        __syncthreads();
        if (kt + 1 < FIN / 64) G_LOAD(kt + 1);
        const int bi = kt & 1;
#pragma unroll
        for (int kp = 0; kp < 4; kp++) {
            const int ch = ((kp * 2 + lhi) ^ lsw) * 16;
            uint4 af[2];
#pragma unroll
            for (int mt = 0; mt < 2; mt++)
                ldsm4(af[mt], sA[bi] + (wm * 32 + mt * 16 + lr) * 128 + ch);
            uint4 bf[2];
#pragma unroll
            for (int bt = 0; bt < 2; bt++)
                ldsm4(bf[bt], sB[bi] + (wn * 32 + bt * 16 + lr) * 128 + ch);
#pragma unroll
            for (int mt = 0; mt < 2; mt++)
#pragma unroll
                for (int bt = 0; bt < 2; bt++) {
                    mma16816(c[mt][2 * bt],     af[mt], bf[bt].x, bf[bt].z);
                    mma16816(c[mt][2 * bt + 1], af[mt], bf[bt].y, bf[bt].w);
                }
        }
        if (kt + 1 < FIN / 64) G_STS((kt + 1) & 1);
    }

    // epilogue: y1 = dinv[r] * xw1[r], fp16  (dinv is ready once g_ready2 is set)
    while (*(volatile int*)&g_ready2 == 0) { __nanosleep(128); }
    __threadfence();
    const int g = lane >> 2, cp = (lane & 3) * 2;
#pragma unroll
    for (int mt = 0; mt < 2; mt++) {
        int r1 = row0 + wm * 32 + mt * 16 + g;
        int r2 = r1 + 8;
        float d1 = (r1 < n) ? g_dinv[r1] : 0.f;
        float d2 = (r2 < n) ? g_dinv[r2] : 0.f;
#pragma unroll
        for (int nt = 0; nt < 4; nt++) {
            int col = wn * 32 + nt * 8 + cp;
            if (r1 < n)
                *(__half2*)&g_y1h[(size_t)r1 * HID + col] =
                    __floats2half2_rn(d1 * c[mt][nt][0], d1 * c[mt][nt][1]);
            if (r2 < n)
                *(__half2*)&g_y1h[(size_t)r2 * HID + col] =
                    __floats2half2_rn(d2 * c[mt][nt][2], d2 * c[mt][nt][3]);
        }
    }
}

// ========== Agg1 + GEMM2 fused: y2 = dinv * (relu(dinv*(sum y1) + b1) @ W2) ==========
// Block = 64 nodes, 256 threads. Phase 1: warp w aggregates nodes w*8..w*8+7 -> h fp16 smem.
// Phase 2: 64x32x128 fp16 MMA vs smem W2^T; epilogue scales rows by dinv -> g_y2 (f32).
__global__ __launch_bounds__(256) void k_aggmm(const float* __restrict__ b1,
                                               const float* __restrict__ W2, int n) {
    __shared__ __align__(16) __half hs[64 * 128];  // 16 KB, 256B rows, swizzled
    __shared__ __align__(16) __half Bs[32 * 128];  // 8 KB, W2^T [n][k], swizzled
    const int tid = threadIdx.x, lane = tid & 31, warp = tid >> 5;
    const int row0 = blockIdx.x * 64;
    const uint32_t sH = smem_u32(hs), sB = smem_u32(Bs);

    // load W2^T fp16 swizzled (all 256 threads)
    {
        const int nn2 = tid >> 3;           // 0..31
        const int kc = (tid & 7) * 16;      // 0..112
        __half tmp[16];
#pragma unroll
        for (int k = 0; k < 16; k++) tmp[k] = __float2half(W2[(size_t)(kc + k) * NCLS + nn2]);
#pragma unroll
        for (int j = 0; j < 2; j++) {
            int cc = kc / 8 + j;
            *(uint4*)((char*)Bs + nn2 * 256 + ((cc ^ (nn2 & 7)) * 16)) = *(uint4*)&tmp[j * 8];
        }
    }

    // phase 1: aggregate (y1 is pre-scaled by dinv_src)
    float4 bb = ((const float4*)b1)[lane];
    const int hc = lane >> 1, hh = (lane & 1) * 8;  // smem chunk / byte-half for store
#pragma unroll 1
    for (int i = 0; i < 8; i++) {
        int node = row0 + warp * 8 + i;
        if (node >= n) break;
        int start = g_rowptr[node];
        int cnt = g_cnt[node];
        float di = g_dinv[node];
        uint2 sv = ((const uint2*)&g_y1h[(size_t)node * HID])[lane];
        float2 s0 = __half22float2(*(__half2*)&sv.x);
        float2 s1 = __half22float2(*(__half2*)&sv.y);
        float4 acc = make_float4(s0.x, s0.y, s1.x, s1.y);  // self term = y1_node
        int t = 0;
        for (; t + 4 <= cnt; t += 4) {
            int e0 = g_csr[start + t],     e1 = g_csr[start + t + 1];
            int e2 = g_csr[start + t + 2], e3 = g_csr[start + t + 3];
            uint2 w0 = ((const uint2*)&g_y1h[(size_t)e0 * HID])[lane];
            uint2 w1 = ((const uint2*)&g_y1h[(size_t)e1 * HID])[lane];
            uint2 w2 = ((const uint2*)&g_y1h[(size_t)e2 * HID])[lane];
            uint2 w3 = ((const uint2*)&g_y1h[(size_t)e3 * HID])[lane];
            float2 a0 = __half22float2(*(__half2*)&w0.x), c0 = __half22float2(*(__half2*)&w0.y);
            float2 a1 = __half22float2(*(__half2*)&w1.x), c1 = __half22float2(*(__half2*)&w1.y);
            float2 a2 = __half22float2(*(__half2*)&w2.x), c2 = __half22float2(*(__half2*)&w2.y);
            float2 a3 = __half22float2(*(__half2*)&w3.x), c3 = __half22float2(*(__half2*)&w3.y);
            acc.x += (a0.x + a1.x) + (a2.x + a3.x);
            acc.y += (a0.y + a1.y) + (a2.y + a3.y);
            acc.z += (c0.x + c1.x) + (c2.x + c3.x);
            acc.w += (c0.y + c1.y) + (c2.y + c3.y);
        }
        for (; t < cnt; t++) {
            int e0 = g_csr[start + t];
            uint2 w0 = ((const uint2*)&g_y1h[(size_t)e0 * HID])[lane];
            float2 a0 = __half22float2(*(__half2*)&w0.x), c0 = __half22float2(*(__half2*)&w0.y);
            acc.x += a0.x; acc.y += a0.y; acc.z += c0.x; acc.w += c0.y;
        }
        float hx = fmaxf(fmaf(di, acc.x, bb.x), 0.f);
        float hy = fmaxf(fmaf(di, acc.y, bb.y), 0.f);
        float hz = fmaxf(fmaf(di, acc.z, bb.z), 0.f);
        float hw = fmaxf(fmaf(di, acc.w, bb.w), 0.f);
        int rl = warp * 8 + i;
        *(uint2*)((char*)hs + rl * 256 + ((hc ^ (rl & 7)) * 16) + hh) =
            make_uint2(packh2(hx, hy), packh2(hz, hw));
    }
    __syncthreads();

    // phase 2: MMA 64x32x128. warp grid: wm = warp&3 (m16 tiles), wn = warp>>2 (n16 tiles)
    const int wm = warp & 3, wn = warp >> 2;
    float c0[4] = {0.f, 0.f, 0.f, 0.f}, c1[4] = {0.f, 0.f, 0.f, 0.f};
    const int lr = lane & 15, lhi = lane >> 4, lsw = lane & 7;
#pragma unroll
    for (int kp = 0; kp < 8; kp++) {
        const int ch = ((kp * 2 + lhi) ^ lsw) * 16;
        uint4 af, bf;
        ldsm4(af, sH + (wm * 16 + lr) * 256 + ch);
        ldsm4(bf, sB + (wn * 16 + lr) * 256 + ch);
        mma16816(c0, af, bf.x, bf.z);
        mma16816(c1, af, bf.y, bf.w);
    }
    const int g = lane >> 2, cp = (lane & 3) * 2;
    int r1 = row0 + wm * 16 + g;
    int r2 = r1 + 8;
    float d1 = (r1 < n) ? g_dinv[r1] : 0.f;
    float d2 = (r2 < n) ? g_dinv[r2] : 0.f;
    int col = wn * 16 + cp;
    if (r1 < n) {
        *(float2*)&g_y2[(size_t)r1 * NCLS + col]     = make_float2(d1 * c0[0], d1 * c0[1]);
        *(float2*)&g_y2[(size_t)r1 * NCLS + col + 8] = make_float2(d1 * c1[0], d1 * c1[1]);
    }
    if (r2 < n) {
        *(float2*)&g_y2[(size_t)r2 * NCLS + col]     = make_float2(d2 * c0[2], d2 * c0[3]);
        *(float2*)&g_y2[(size_t)r2 * NCLS + col + 8] = make_float2(d2 * c1[2], d2 * c1[3]);
    }
}

// ---------------- Agg2 + log_softmax: 4 edge-groups/warp, y2 pre-scaled ----------------
__global__ __launch_bounds__(256) void k_agg2(const float* __restrict__ b2,
                                              float* __restrict__ out, int n) {
    const int tid = threadIdx.x, lane = tid & 31;
    const int grp = lane >> 3, li = lane & 7;
    int node = blockIdx.x * 8 + (tid >> 5);
    if (node >= n) return;
    int start = g_rowptr[node];
    int cnt = g_cnt[node];
    float di = g_dinv[node];
    float4 acc = make_float4(0.f, 0.f, 0.f, 0.f);
    if (grp == 0) {
        float4 s = ((const float4*)&g_y2[(size_t)node * NCLS])[li];
        acc = s;  // self term = y2_node
    }
    for (int t = grp; t < cnt; t += 4) {
        int s = g_csr[start + t];
        float4 w = ((const float4*)&g_y2[(size_t)s * NCLS])[li];
        acc.x += w.x; acc.y += w.y; acc.z += w.z; acc.w += w.w;
    }
#pragma unroll
    for (int o = 8; o <= 16; o <<= 1) {
        acc.x += __shfl_xor_sync(0xffffffffu, acc.x, o);
        acc.y += __shfl_xor_sync(0xffffffffu, acc.y, o);
        acc.z += __shfl_xor_sync(0xffffffffu, acc.z, o);
        acc.w += __shfl_xor_sync(0xffffffffu, acc.w, o);
    }
    float4 bb = ((const float4*)b2)[li];
    float4 vv = make_float4(fmaf(di, acc.x, bb.x), fmaf(di, acc.y, bb.y),
                            fmaf(di, acc.z, bb.z), fmaf(di, acc.w, bb.w));
    float m = fmaxf(fmaxf(vv.x, vv.y), fmaxf(vv.z, vv.w));
#pragma unroll
    for (int o = 1; o <= 4; o <<= 1) m = fmaxf(m, __shfl_xor_sync(0xffffffffu, m, o));
    float s4 = __expf(vv.x - m) + __expf(vv.y - m) + __expf(vv.z - m) + __expf(vv.w - m);
#pragma unroll
    for (int o = 1; o <= 4; o <<= 1) s4 += __shfl_xor_sync(0xffffffffu, s4, o);
    float ls = m + logf(s4);
    if (lane < 8)
        ((float4*)&out[(size_t)node * NCLS])[li] =
            make_float4(vv.x - ls, vv.y - ls, vv.z - ls, vv.w - ls);
}

// ---------------- launch ----------------
extern "C" void kernel_launch(void* const* d_in, const int* in_sizes, int n_in,
                              void* d_out, int out_size) {
    const float* X = (const float*)d_in[0];
    const void* EI = d_in[1];
    const float* W1 = (const float*)d_in[2];
    const float* b1 = (const float*)d_in[3];
    const float* W2 = (const float*)d_in[4];
    const float* b2 = (const float*)d_in[5];
    float* out = (float*)d_out;

    int n = in_sizes[0] / FIN;   // 100000
    int e = in_sizes[1] / 2;     // 800000

    static int smem_set = 0;
    if (!smem_set) {
        cudaFuncSetAttribute(k_fat, cudaFuncAttributeMaxDynamicSharedMemorySize, 65536);
        smem_set = 1;
    }

    int g1blocks = (n + 127) / 128;  // 782
    k_fat<<<NPRE + g1blocks, 512, 65536>>>(X, W1, EI, n, e);
    k_aggmm<<<(n + 63) / 64, 256>>>(b1, W2, n);
    k_agg2<<<(n + 7) / 8, 256>>>(b2, out, n);
}

// round 10
// speedup vs baseline: 2.2210x; 1.0730x over previous
#include <cuda_runtime.h>
#include <cuda_fp16.h>
#include <cstdint>

#define NN 100000
#define NE 800000
#define FIN 256
#define HID 128
#define NCLS 32
#define NPRE 128

// ---------------- scratch ----------------
__device__ int   g_cnt[NN];
__device__ int   g_rowptr[NN];
__device__ int   g_cursor[NN];
__device__ int   g_part[NPRE];
__device__ float g_dinv[NN];
__device__ int   g_csr[NE];
__device__ int   g_is64;
__device__ int   g_ready = 0;
__device__ int   g_ready2 = 0;
__device__ unsigned g_bar_cnt = 0;
__device__ volatile unsigned g_bar_gen = 0;
__device__ __align__(16) __half g_y1h[(size_t)NN * HID];   // dinv * (X@W1), fp16
__device__ __align__(16) float  g_y2[(size_t)NN * NCLS];   // dinv * (h@W2), f32
__device__ __align__(16) __half g_W1h[HID * FIN];          // W1^T fp16 [n][k]

// ---------------- helpers ----------------
__device__ __forceinline__ int load_idx(const void* p, long long i, int is64) {
    if (is64) return (int)((const long long*)p)[i];
    return ((const int*)p)[i];
}
__device__ __forceinline__ uint32_t smem_u32(const void* p) {
    uint32_t a;
    asm("{ .reg .u64 t; cvta.to.shared.u64 t, %1; cvt.u32.u64 %0, t; }" : "=r"(a) : "l"(p));
    return a;
}
__device__ __forceinline__ void ldsm4(uint4& r, uint32_t addr) {
    asm volatile("ldmatrix.sync.aligned.m8n8.x4.shared.b16 {%0,%1,%2,%3}, [%4];"
                 : "=r"(r.x), "=r"(r.y), "=r"(r.z), "=r"(r.w) : "r"(addr));
}
__device__ __forceinline__ void mma16816(float c[4], const uint4& a, uint32_t b0, uint32_t b1) {
    asm volatile(
        "mma.sync.aligned.m16n8k16.row.col.f32.f16.f16.f32 "
        "{%0,%1,%2,%3}, {%4,%5,%6,%7}, {%8,%9}, {%0,%1,%2,%3};"
        : "+f"(c[0]), "+f"(c[1]), "+f"(c[2]), "+f"(c[3])
        : "r"(a.x), "r"(a.y), "r"(a.z), "r"(a.w), "r"(b0), "r"(b1));
}
__device__ __forceinline__ uint32_t packh2(float a, float b) {
    __half2 h = __floats2half2_rn(a, b);
    return *(uint32_t*)&h;
}
__device__ __forceinline__ void cpasync16(uint32_t dst, const void* src) {
    asm volatile("cp.async.cg.shared.global [%0], [%1], 16;" :: "r"(dst), "l"(src));
}
#define CP_COMMIT() asm volatile("cp.async.commit_group;" ::: "memory")
#define CP_WAIT0()  asm volatile("cp.async.wait_group 0;" ::: "memory")

__device__ __forceinline__ void pre_grid_bar() {
    __syncthreads();
    if (threadIdx.x == 0) {
        __threadfence();
        unsigned g = g_bar_gen;
        if (atomicAdd(&g_bar_cnt, 1u) == NPRE - 1) {
            g_bar_cnt = 0;
            __threadfence();
            g_bar_gen = g + 1;
        } else {
            while (g_bar_gen == g) { __nanosleep(64); }
        }
    }
    __syncthreads();
}

__device__ __forceinline__ int block_exscan(int v, int* p_total, int* wsum) {
    const int lane = threadIdx.x & 31, w = threadIdx.x >> 5;
    const int nw = blockDim.x >> 5;
    int x = v;
#pragma unroll
    for (int o = 1; o < 32; o <<= 1) {
        int y = __shfl_up_sync(0xffffffffu, x, o);
        if (lane >= o) x += y;
    }
    if (lane == 31) wsum[w] = x;
    __syncthreads();
    if (w == 0) {
        int s = (lane < nw) ? wsum[lane] : 0;
#pragma unroll
        for (int o = 1; o < 32; o <<= 1) {
            int y = __shfl_up_sync(0xffffffffu, s, o);
            if (lane >= o) s += y;
        }
        wsum[lane] = s;
    }
    __syncthreads();
    int base = (w > 0) ? wsum[w - 1] : 0;
    *p_total = wsum[31];
    __syncthreads();
    return base + (x - v);
}

// ================= FAT: preproc (blocks < NPRE) + fp16-MMA GEMM1 via cp.async =================
// GEMM dyn smem (96 KB): [0,32K) A32 staging f32; [32K,64K) A16[2]; [64K,96K) B16[2]
__global__ __launch_bounds__(512, 2) void k_fat(const float* __restrict__ X,
                                                const float* __restrict__ W1,
                                                const void* __restrict__ ei,
                                                int n, int e) {
    extern __shared__ char dsm[];
    __shared__ int p_wsum[32];
    __shared__ int p_boff;
    const int tid = threadIdx.x;

    if (blockIdx.x < NPRE) {
        const int gt = blockIdx.x * 512 + tid;
        const int GT = NPRE * 512;
        for (int i = gt; i < n; i += GT) g_cnt[i] = 0;
        for (int i = gt; i < HID * FIN; i += GT) {
            int nn2 = i >> 8, k = i & 255;
            g_W1h[i] = __float2half(W1[(size_t)k * HID + nn2]);
        }
        if (gt == 0) {
            const long long* p = (const long long*)ei;
            int ok = 1;
            for (int j = 0; j < 256; j++) {
                long long v = p[j];
                if (v < 0 || v >= n) { ok = 0; break; }
            }
            g_is64 = ok;
        }
        pre_grid_bar();
        if (blockIdx.x == 0 && tid == 0) *(volatile int*)&g_ready = 1;
        const int is64 = g_is64;
        for (int i = gt; i < e; i += GT) {
            int d = load_idx(ei, (long long)e + i, is64);
            atomicAdd(&g_cnt[d], 1);
        }
        pre_grid_bar();
        const int L = (n + GT - 1) / GT;
        const int base = gt * L;
        const int end = (base + L < n) ? base + L : n;
        int s = 0;
        for (int i = base; i < end; i++) s += __ldcg(&g_cnt[i]);
        int tot;
        int ex = block_exscan(s, &tot, p_wsum);
        if (tid == 0) g_part[blockIdx.x] = tot;
        pre_grid_bar();
        {
            int v = (tid < NPRE) ? __ldcg(&g_part[tid]) : 0;
            int t2;
            int ex2 = block_exscan(v, &t2, p_wsum);
            if (tid == (int)blockIdx.x) p_boff = ex2;
            __syncthreads();
            int run = p_boff + ex;
            for (int i = base; i < end; i++) {
                int c = __ldcg(&g_cnt[i]);
                g_rowptr[i] = run;
                g_cursor[i] = run;
                g_dinv[i] = rsqrtf((float)(c + 1));
                run += c;
            }
        }
        pre_grid_bar();
        if (blockIdx.x == 0 && tid == 0) *(volatile int*)&g_ready2 = 1;
        for (int i = gt; i < e; i += GT) {
            int s0 = load_idx(ei, i, is64);
            int d0 = load_idx(ei, (long long)e + i, is64);
            int pos = atomicAdd(&g_cursor[d0], 1);
            g_csr[pos] = s0;
        }
        return;
    }

    // -------- GEMM1: 128x128 tile, BK=64, cp.async pipeline, warp grid 4x4 --------
    while (*(volatile int*)&g_ready == 0) { __nanosleep(128); }
    __threadfence();

    const int bid = blockIdx.x - NPRE;
    const int row0 = bid * 128;
    const int lane = tid & 31, warp = tid >> 5;
    const int wm = warp & 3, wn = warp >> 2;
    const uint32_t sbase = smem_u32(dsm);
    const uint32_t sA32 = sbase;
    const uint32_t sA16[2] = { sbase + 32768, sbase + 49152 };
    const uint32_t sB16[2] = { sbase + 65536, sbase + 81920 };

    float c[2][4][4];
#pragma unroll
    for (int i = 0; i < 2; i++)
#pragma unroll
        for (int j = 0; j < 4; j++)
#pragma unroll
            for (int v = 0; v < 4; v++) c[i][j][v] = 0.f;

    // loader indices: thread -> row lrow = tid>>2 (0..127), quarter lq = tid&3
    const int lrow = tid >> 2;
    const int lq = tid & 3;
    const int rsw = lrow & 7;
    int arow = row0 + lrow; if (arow >= n) arow = n - 1;
    const char* agp = (const char*)(X + (size_t)arow * FIN);      // 1024 B/row
    const char* bgp = (const char*)(g_W1h + (size_t)lrow * FIN);  // 512 B/row

    // A32 staging: row-major 128 x 256B. cp.async 4x16B per thread.
#define ISSUE_A32(kt) do {                                                    \
        _Pragma("unroll")                                                     \
        for (int j = 0; j < 4; j++)                                           \
            cpasync16(sA32 + lrow * 256 + lq * 64 + j * 16,                   \
                      agp + (kt) * 256 + lq * 64 + j * 16);                   \
    } while (0)
    // B16: swizzled rows of 128B (8 chunks). cp.async 2x16B per thread.
#define ISSUE_B(kt, bi) do {                                                  \
        _Pragma("unroll")                                                     \
        for (int j = 0; j < 2; j++) {                                         \
            int cc = lq * 2 + j;                                              \
            cpasync16(sB16[bi] + lrow * 128 + ((cc ^ rsw) * 16),              \
                      bgp + (kt) * 128 + cc * 16);                            \
        }                                                                     \
    } while (0)
    // convert A32 (f32) -> A16[bi] (fp16, swizzled). 2 chunks per thread.
#define CONVERT_A(bi) do {                                                    \
        _Pragma("unroll")                                                     \
        for (int j = 0; j < 2; j++) {                                         \
            int cc = lq * 2 + j;                                              \
            float4 v0, v1;                                                    \
            asm volatile("ld.shared.v4.f32 {%0,%1,%2,%3}, [%4];"              \
                : "=f"(v0.x), "=f"(v0.y), "=f"(v0.z), "=f"(v0.w)              \
                : "r"(sA32 + lrow * 256 + cc * 32));                          \
            asm volatile("ld.shared.v4.f32 {%0,%1,%2,%3}, [%4];"              \
                : "=f"(v1.x), "=f"(v1.y), "=f"(v1.z), "=f"(v1.w)              \
                : "r"(sA32 + lrow * 256 + cc * 32 + 16));                     \
            uint4 u = make_uint4(packh2(v0.x, v0.y), packh2(v0.z, v0.w),      \
                                 packh2(v1.x, v1.y), packh2(v1.z, v1.w));     \
            asm volatile("st.shared.v4.b32 [%0], {%1,%2,%3,%4};"              \
                :: "r"(sA16[bi] + lrow * 128 + ((cc ^ rsw) * 16)),            \
                   "r"(u.x), "r"(u.y), "r"(u.z), "r"(u.w));                   \
        }                                                                     \
    } while (0)

    ISSUE_A32(0); ISSUE_B(0, 0); CP_COMMIT();
    CP_WAIT0(); __syncthreads();
    CONVERT_A(0); __syncthreads();
    ISSUE_A32(1); ISSUE_B(1, 1); CP_COMMIT();

    const int lr = lane & 15, lhi = lane >> 4, lsw = lane & 7;
    for (int kt = 0; kt < FIN / 64; kt++) {
        const int bi = kt & 1;
#pragma unroll
        for (int kp = 0; kp < 4; kp++) {
            const int ch = ((kp * 2 + lhi) ^ lsw) * 16;
            uint4 af[2];
#pragma unroll
            for (int mt = 0; mt < 2; mt++)
                ldsm4(af[mt], sA16[bi] + (wm * 32 + mt * 16 + lr) * 128 + ch);
            uint4 bf[2];
#pragma unroll
            for (int bt = 0; bt < 2; bt++)
                ldsm4(bf[bt], sB16[bi] + (wn * 32 + bt * 16 + lr) * 128 + ch);
#pragma unroll
            for (int mt = 0; mt < 2; mt++)
#pragma unroll
                for (int bt = 0; bt < 2; bt++) {
                    mma16816(c[mt][2 * bt],     af[mt], bf[bt].x, bf[bt].z);
                    mma16816(c[mt][2 * bt + 1], af[mt], bf[bt].y, bf[bt].w);
                }
        }
        if (kt + 1 < FIN / 64) {
            CP_WAIT0(); __syncthreads();
            CONVERT_A((kt + 1) & 1);
            __syncthreads();
            if (kt + 2 < FIN / 64) { ISSUE_A32(kt + 2); ISSUE_B(kt + 2, (kt + 2) & 1); CP_COMMIT(); }
        }
    }

    // epilogue: y1 = dinv[r] * xw1[r], fp16
    while (*(volatile int*)&g_ready2 == 0) { __nanosleep(128); }
    __threadfence();
    const int g = lane >> 2, cp = (lane & 3) * 2;
#pragma unroll
    for (int mt = 0; mt < 2; mt++) {
        int r1 = row0 + wm * 32 + mt * 16 + g;
        int r2 = r1 + 8;
        float d1 = (r1 < n) ? g_dinv[r1] : 0.f;
        float d2 = (r2 < n) ? g_dinv[r2] : 0.f;
#pragma unroll
        for (int nt = 0; nt < 4; nt++) {
            int col = wn * 32 + nt * 8 + cp;
            if (r1 < n)
                *(__half2*)&g_y1h[(size_t)r1 * HID + col] =
                    __floats2half2_rn(d1 * c[mt][nt][0], d1 * c[mt][nt][1]);
            if (r2 < n)
                *(__half2*)&g_y1h[(size_t)r2 * HID + col] =
                    __floats2half2_rn(d2 * c[mt][nt][2], d2 * c[mt][nt][3]);
        }
    }
}

// ========== Agg1 + GEMM2 fused: y2 = dinv * (relu(dinv*(sum y1) + b1) @ W2) ==========
__global__ __launch_bounds__(256) void k_aggmm(const float* __restrict__ b1,
                                               const float* __restrict__ W2, int n) {
    __shared__ __align__(16) __half hs[64 * 128];  // 16 KB
    __shared__ __align__(16) __half Bs[32 * 128];  // 8 KB
    const int tid = threadIdx.x, lane = tid & 31, warp = tid >> 5;
    const int row0 = blockIdx.x * 64;
    const uint32_t sH = smem_u32(hs), sB = smem_u32(Bs);

    {
        const int nn2 = tid >> 3;
        const int kc = (tid & 7) * 16;
        __half tmp[16];
#pragma unroll
        for (int k = 0; k < 16; k++) tmp[k] = __float2half(W2[(size_t)(kc + k) * NCLS + nn2]);
#pragma unroll
        for (int j = 0; j < 2; j++) {
            int cc = kc / 8 + j;
            *(uint4*)((char*)Bs + nn2 * 256 + ((cc ^ (nn2 & 7)) * 16)) = *(uint4*)&tmp[j * 8];
        }
    }

    float4 bb = ((const float4*)b1)[lane];
    const int hc = lane >> 1, hh = (lane & 1) * 8;
#pragma unroll 1
    for (int i = 0; i < 8; i++) {
        int node = row0 + warp * 8 + i;
        if (node >= n) break;
        int start = g_rowptr[node];
        int cnt = g_cnt[node];
        float di = g_dinv[node];
        uint2 sv = ((const uint2*)&g_y1h[(size_t)node * HID])[lane];
        float2 s0 = __half22float2(*(__half2*)&sv.x);
        float2 s1 = __half22float2(*(__half2*)&sv.y);
        float4 acc = make_float4(s0.x, s0.y, s1.x, s1.y);
        int t = 0;
        for (; t + 4 <= cnt; t += 4) {
            int e0 = g_csr[start + t],     e1 = g_csr[start + t + 1];
            int e2 = g_csr[start + t + 2], e3 = g_csr[start + t + 3];
            uint2 w0 = ((const uint2*)&g_y1h[(size_t)e0 * HID])[lane];
            uint2 w1 = ((const uint2*)&g_y1h[(size_t)e1 * HID])[lane];
            uint2 w2 = ((const uint2*)&g_y1h[(size_t)e2 * HID])[lane];
            uint2 w3 = ((const uint2*)&g_y1h[(size_t)e3 * HID])[lane];
            float2 a0 = __half22float2(*(__half2*)&w0.x), c0 = __half22float2(*(__half2*)&w0.y);
            float2 a1 = __half22float2(*(__half2*)&w1.x), c1 = __half22float2(*(__half2*)&w1.y);
            float2 a2 = __half22float2(*(__half2*)&w2.x), c2 = __half22float2(*(__half2*)&w2.y);
            float2 a3 = __half22float2(*(__half2*)&w3.x), c3 = __half22float2(*(__half2*)&w3.y);
            acc.x += (a0.x + a1.x) + (a2.x + a3.x);
            acc.y += (a0.y + a1.y) + (a2.y + a3.y);
            acc.z += (c0.x + c1.x) + (c2.x + c3.x);
            acc.w += (c0.y + c1.y) + (c2.y + c3.y);
        }
        for (; t < cnt; t++) {
            int e0 = g_csr[start + t];
            uint2 w0 = ((const uint2*)&g_y1h[(size_t)e0 * HID])[lane];
            float2 a0 = __half22float2(*(__half2*)&w0.x), c0 = __half22float2(*(__half2*)&w0.y);
            acc.x += a0.x; acc.y += a0.y; acc.z += c0.x; acc.w += c0.y;
        }
        float hx = fmaxf(fmaf(di, acc.x, bb.x), 0.f);
        float hy = fmaxf(fmaf(di, acc.y, bb.y), 0.f);
        float hz = fmaxf(fmaf(di, acc.z, bb.z), 0.f);
        float hw = fmaxf(fmaf(di, acc.w, bb.w), 0.f);
        int rl = warp * 8 + i;
        *(uint2*)((char*)hs + rl * 256 + ((hc ^ (rl & 7)) * 16) + hh) =
            make_uint2(packh2(hx, hy), packh2(hz, hw));
    }
    __syncthreads();

    const int wm = warp & 3, wn = warp >> 2;
    float c0[4] = {0.f, 0.f, 0.f, 0.f}, c1[4] = {0.f, 0.f, 0.f, 0.f};
    const int lr = lane & 15, lhi = lane >> 4, lsw = lane & 7;
#pragma unroll
    for (int kp = 0; kp < 8; kp++) {
        const int ch = ((kp * 2 + lhi) ^ lsw) * 16;
        uint4 af, bf;
        ldsm4(af, sH + (wm * 16 + lr) * 256 + ch);
        ldsm4(bf, sB + (wn * 16 + lr) * 256 + ch);
        mma16816(c0, af, bf.x, bf.z);
        mma16816(c1, af, bf.y, bf.w);
    }
    const int g = lane >> 2, cp = (lane & 3) * 2;
    int r1 = row0 + wm * 16 + g;
    int r2 = r1 + 8;
    float d1 = (r1 < n) ? g_dinv[r1] : 0.f;
    float d2 = (r2 < n) ? g_dinv[r2] : 0.f;
    int col = wn * 16 + cp;
    if (r1 < n) {
        *(float2*)&g_y2[(size_t)r1 * NCLS + col]     = make_float2(d1 * c0[0], d1 * c0[1]);
        *(float2*)&g_y2[(size_t)r1 * NCLS + col + 8] = make_float2(d1 * c1[0], d1 * c1[1]);
    }
    if (r2 < n) {
        *(float2*)&g_y2[(size_t)r2 * NCLS + col]     = make_float2(d2 * c0[2], d2 * c0[3]);
        *(float2*)&g_y2[(size_t)r2 * NCLS + col + 8] = make_float2(d2 * c1[2], d2 * c1[3]);
    }
}

// ---------------- Agg2 + log_softmax ----------------
__global__ __launch_bounds__(256) void k_agg2(const float* __restrict__ b2,
                                              float* __restrict__ out, int n) {
    const int tid = threadIdx.x, lane = tid & 31;
    const int grp = lane >> 3, li = lane & 7;
    int node = blockIdx.x * 8 + (tid >> 5);
    if (node >= n) return;
    int start = g_rowptr[node];
    int cnt = g_cnt[node];
    float di = g_dinv[node];
    float4 acc = make_float4(0.f, 0.f, 0.f, 0.f);
    if (grp == 0) acc = ((const float4*)&g_y2[(size_t)node * NCLS])[li];
    for (int t = grp; t < cnt; t += 4) {
        int s = g_csr[start + t];
        float4 w = ((const float4*)&g_y2[(size_t)s * NCLS])[li];
        acc.x += w.x; acc.y += w.y; acc.z += w.z; acc.w += w.w;
    }
#pragma unroll
    for (int o = 8; o <= 16; o <<= 1) {
        acc.x += __shfl_xor_sync(0xffffffffu, acc.x, o);
        acc.y += __shfl_xor_sync(0xffffffffu, acc.y, o);
        acc.z += __shfl_xor_sync(0xffffffffu, acc.z, o);
        acc.w += __shfl_xor_sync(0xffffffffu, acc.w, o);
    }
    float4 bb = ((const float4*)b2)[li];
    float4 vv = make_float4(fmaf(di, acc.x, bb.x), fmaf(di, acc.y, bb.y),
                            fmaf(di, acc.z, bb.z), fmaf(di, acc.w, bb.w));
    float m = fmaxf(fmaxf(vv.x, vv.y), fmaxf(vv.z, vv.w));
#pragma unroll
    for (int o = 1; o <= 4; o <<= 1) m = fmaxf(m, __shfl_xor_sync(0xffffffffu, m, o));
    float s4 = __expf(vv.x - m) + __expf(vv.y - m) + __expf(vv.z - m) + __expf(vv.w - m);
#pragma unroll
    for (int o = 1; o <= 4; o <<= 1) s4 += __shfl_xor_sync(0xffffffffu, s4, o);
    float ls = m + logf(s4);
    if (lane < 8)
        ((float4*)&out[(size_t)node * NCLS])[li] =
            make_float4(vv.x - ls, vv.y - ls, vv.z - ls, vv.w - ls);
}

// ---------------- launch ----------------
extern "C" void kernel_launch(void* const* d_in, const int* in_sizes, int n_in,
                              void* d_out, int out_size) {
    const float* X = (const float*)d_in[0];
    const void* EI = d_in[1];
    const float* W1 = (const float*)d_in[2];
    const float* b1 = (const float*)d_in[3];
    const float* W2 = (const float*)d_in[4];
    const float* b2 = (const float*)d_in[5];
    float* out = (float*)d_out;

    int n = in_sizes[0] / FIN;   // 100000
    int e = in_sizes[1] / 2;     // 800000

    static int smem_set = 0;
    if (!smem_set) {
        cudaFuncSetAttribute(k_fat, cudaFuncAttributeMaxDynamicSharedMemorySize, 98304);
        smem_set = 1;
    }

    int g1blocks = (n + 127) / 128;  // 782
    k_fat<<<NPRE + g1blocks, 512, 98304>>>(X, W1, EI, n, e);
    k_aggmm<<<(n + 63) / 64, 256>>>(b1, W2, n);
    k_agg2<<<(n + 7) / 8, 256>>>(b2, out, n);
}